// round 12
// baseline (speedup 1.0000x reference)
#include <cuda_runtime.h>
#include <cuda_bf16.h>
#include <mma.h>
#include <cstdint>
#include <math.h>

using namespace nvcuda;

#define B_    4
#define DE    128
#define DO    512
#define THW   10240
#define HW    1024
#define NCHUNK 80
#define SCALE 0.08838834764831845f
#define INV2SIG2 (1.0f/18.0f)

// ---------------- device scratch ----------------
__device__ float         g_p[(size_t)B_ * THW * HW];       // p fp32 (preserved)
__device__ __nv_bfloat16 g_ehi[(size_t)B_ * HW * THW];     // e^T [b][q][t] hi
__device__ __nv_bfloat16 g_elo[(size_t)B_ * HW * THW];
__device__ __nv_bfloat16 g_mohi[(size_t)B_ * DO * THW];
__device__ __nv_bfloat16 g_molo[(size_t)B_ * DO * THW];
__device__ __nv_bfloat16 g_mi0[(size_t)B_ * DE * THW];     // mi 3 limbs [b][d][t]
__device__ __nv_bfloat16 g_mi1[(size_t)B_ * DE * THW];
__device__ __nv_bfloat16 g_mi2[(size_t)B_ * DE * THW];
__device__ __nv_bfloat16 g_qi0[(size_t)B_ * DE * HW];      // qi*SCALE 3 limbs [b][d][q]
__device__ __nv_bfloat16 g_qi1[(size_t)B_ * DE * HW];
__device__ __nv_bfloat16 g_qi2[(size_t)B_ * DE * HW];
__device__ float         g_cpart[(size_t)2 * B_ * DO * HW]; // split-K partials
__device__ float2        g_center[B_ * THW];
__device__ float2        g_amax[(size_t)B_ * THW * 8];     // per-qtile argmax partials
__device__ float         g_part[(size_t)B_ * NCHUNK * HW];
__device__ float         g_inv[B_ * HW];

__device__ __forceinline__ void cp16(uint32_t sa, const void* g) {
    asm volatile("cp.async.cg.shared.global [%0], [%1], 16;" :: "r"(sa), "l"(g));
}
#define CP_COMMIT() asm volatile("cp.async.commit_group;" ::: "memory")
#define CP_WAIT(n)  asm volatile("cp.async.wait_group %0;" :: "n"(n) : "memory")

// ============================================================
// split fp32 -> 3 bf16 limbs (optional scale)
// ============================================================
__global__ void __launch_bounds__(256) split3_kernel(
    const float* __restrict__ in, __nv_bfloat16* __restrict__ o0,
    __nv_bfloat16* __restrict__ o1, __nv_bfloat16* __restrict__ o2,
    size_t n4, float scale)
{
    const size_t stride = (size_t)gridDim.x * 256;
    for (size_t i = (size_t)blockIdx.x * 256 + threadIdx.x; i < n4; i += stride) {
        float4 v = ((const float4*)in)[i];
        v.x *= scale; v.y *= scale; v.z *= scale; v.w *= scale;
        float f[4] = {v.x, v.y, v.z, v.w};
        uint16_t l0[4], l1[4], l2[4];
        #pragma unroll
        for (int k = 0; k < 4; k++) {
            __nv_bfloat16 h0 = __float2bfloat16(f[k]);
            float r = f[k] - __bfloat162float(h0);
            __nv_bfloat16 h1 = __float2bfloat16(r);
            float r2 = r - __bfloat162float(h1);
            __nv_bfloat16 h2 = __float2bfloat16(r2);
            l0[k] = *(uint16_t*)&h0; l1[k] = *(uint16_t*)&h1; l2[k] = *(uint16_t*)&h2;
        }
        ((uint2*)o0)[i] = make_uint2(l0[0] | ((uint32_t)l0[1] << 16), l0[2] | ((uint32_t)l0[3] << 16));
        ((uint2*)o1)[i] = make_uint2(l1[0] | ((uint32_t)l1[1] << 16), l1[2] | ((uint32_t)l1[3] << 16));
        ((uint2*)o2)[i] = make_uint2(l2[0] | ((uint32_t)l2[1] << 16), l2[2] | ((uint32_t)l2[3] << 16));
    }
}

// mo fp32 -> bf16 hi/lo (2 limbs, for GEMM2)
__global__ void __launch_bounds__(256) split_kernel(const float* __restrict__ in)
{
    const size_t n4 = (size_t)B_ * DO * THW / 4;
    const size_t stride = (size_t)gridDim.x * 256;
    for (size_t i = (size_t)blockIdx.x * 256 + threadIdx.x; i < n4; i += stride) {
        float4 v = ((const float4*)in)[i];
        __nv_bfloat16 h0 = __float2bfloat16(v.x), h1 = __float2bfloat16(v.y);
        __nv_bfloat16 h2 = __float2bfloat16(v.z), h3 = __float2bfloat16(v.w);
        __nv_bfloat162* H = (__nv_bfloat162*)g_mohi;
        __nv_bfloat162* L = (__nv_bfloat162*)g_molo;
        H[2*i]   = __halves2bfloat162(h0, h1);
        H[2*i+1] = __halves2bfloat162(h2, h3);
        L[2*i]   = __halves2bfloat162(__float2bfloat16(v.x - __bfloat162float(h0)),
                                      __float2bfloat16(v.y - __bfloat162float(h1)));
        L[2*i+1] = __halves2bfloat162(__float2bfloat16(v.z - __bfloat162float(h2)),
                                      __float2bfloat16(v.w - __bfloat162float(h3)));
    }
}

// ============================================================
// WMMA bf16 GEMM1 (3-limb, 6 passes): p = (mi)^T (qi*SCALE)
// 256 threads / 8 warps (4x2), warp tile 32(t) x 64(q), 2 CTAs/SM
// inner loop ordered pass-outermost: 8 independent mma between
// successive accumulations into the same fragment
// ============================================================
#define TP 136
#define G1_TILE (32 * TP)
#define G1_STAGE (6 * G1_TILE)
#define G1_SMEM (2 * G1_STAGE * 2)              // 104448 bytes

__global__ void __launch_bounds__(256, 2) gemm1_wmma(float* __restrict__ p)
{
    extern __shared__ __nv_bfloat16 dsm[];
    const int b = blockIdx.z;
    const int q0 = blockIdx.x * 128, t0 = blockIdx.y * 128;
    const int tid = threadIdx.x, wid = tid >> 5;
    const int wm = wid & 3, wn = wid >> 2;       // warp tile 32(t) x 64(q)

    const __nv_bfloat16* A0 = g_mi0 + (size_t)b * DE * THW;
    const __nv_bfloat16* A1 = g_mi1 + (size_t)b * DE * THW;
    const __nv_bfloat16* A2 = g_mi2 + (size_t)b * DE * THW;
    const __nv_bfloat16* B0 = g_qi0 + (size_t)b * DE * HW;
    const __nv_bfloat16* B1 = g_qi1 + (size_t)b * DE * HW;
    const __nv_bfloat16* B2 = g_qi2 + (size_t)b * DE * HW;

    const uint32_t sbase = (uint32_t)__cvta_generic_to_shared(dsm);

    auto load_stage = [&](int slot, int k0) {
        uint32_t sb = sbase + (uint32_t)slot * (G1_STAGE * 2);
        #pragma unroll
        for (int l = 0; l < 12; l++) {
            int idx = tid + l * 256;             // 0..3071
            int arr = idx >> 9, rem = idx & 511;
            int row = rem >> 4, col = rem & 15;  // row<32 (d), col*8 elems
            const __nv_bfloat16* src;
            if (arr < 3) {
                src = (arr == 0 ? A0 : arr == 1 ? A1 : A2)
                      + (size_t)(k0 + row) * THW + t0 + col * 8;
            } else {
                src = (arr == 3 ? B0 : arr == 4 ? B1 : B2)
                      + (size_t)(k0 + row) * HW + q0 + col * 8;
            }
            cp16(sb + (uint32_t)arr * (G1_TILE * 2) + row * (TP * 2) + col * 16, src);
        }
    };

    wmma::fragment<wmma::accumulator, 16, 16, 16, float> fc[2][4];
    #pragma unroll
    for (int i = 0; i < 2; i++)
        #pragma unroll
        for (int j = 0; j < 4; j++) wmma::fill_fragment(fc[i][j], 0.f);

    const int NC = DE / 32;   // 4
    load_stage(0, 0);
    CP_COMMIT();

    for (int c = 0; c < NC; c++) {
        if (c + 1 < NC) { load_stage((c + 1) & 1, (c + 1) * 32); CP_COMMIT(); }
        if (c + 1 < NC) CP_WAIT(1); else CP_WAIT(0);
        __syncthreads();

        __nv_bfloat16* st = dsm + (size_t)(c & 1) * G1_STAGE;
        #pragma unroll
        for (int kk = 0; kk < 32; kk += 16) {
            wmma::fragment<wmma::matrix_a, 16, 16, 16, __nv_bfloat16, wmma::col_major> fa[3][2];
            #pragma unroll
            for (int l = 0; l < 3; l++)
                #pragma unroll
                for (int i = 0; i < 2; i++)
                    wmma::load_matrix_sync(fa[l][i],
                        st + l * G1_TILE + kk * TP + wm * 32 + i * 16, TP);
            // B limb 0: passes A0, A1, A2 — pass OUTER, 8 indep mma per pass
            {
                wmma::fragment<wmma::matrix_b, 16, 16, 16, __nv_bfloat16, wmma::row_major> fb[4];
                #pragma unroll
                for (int j = 0; j < 4; j++)
                    wmma::load_matrix_sync(fb[j],
                        st + 3 * G1_TILE + kk * TP + wn * 64 + j * 16, TP);
                #pragma unroll
                for (int l = 0; l < 3; l++)
                    #pragma unroll
                    for (int i = 0; i < 2; i++)
                        #pragma unroll
                        for (int j = 0; j < 4; j++)
                            wmma::mma_sync(fc[i][j], fa[l][i], fb[j], fc[i][j]);
            }
            // B limb 1: passes A0, A1
            {
                wmma::fragment<wmma::matrix_b, 16, 16, 16, __nv_bfloat16, wmma::row_major> fb[4];
                #pragma unroll
                for (int j = 0; j < 4; j++)
                    wmma::load_matrix_sync(fb[j],
                        st + 4 * G1_TILE + kk * TP + wn * 64 + j * 16, TP);
                #pragma unroll
                for (int l = 0; l < 2; l++)
                    #pragma unroll
                    for (int i = 0; i < 2; i++)
                        #pragma unroll
                        for (int j = 0; j < 4; j++)
                            wmma::mma_sync(fc[i][j], fa[l][i], fb[j], fc[i][j]);
            }
            // B limb 2: pass A0
            {
                wmma::fragment<wmma::matrix_b, 16, 16, 16, __nv_bfloat16, wmma::row_major> fb[4];
                #pragma unroll
                for (int j = 0; j < 4; j++)
                    wmma::load_matrix_sync(fb[j],
                        st + 5 * G1_TILE + kk * TP + wn * 64 + j * 16, TP);
                #pragma unroll
                for (int i = 0; i < 2; i++)
                    #pragma unroll
                    for (int j = 0; j < 4; j++)
                        wmma::mma_sync(fc[i][j], fa[0][i], fb[j], fc[i][j]);
            }
        }
        __syncthreads();
    }

    // epilogue via smem: 128x128 fp32 tile
    float* sc = (float*)dsm;
    #pragma unroll
    for (int i = 0; i < 2; i++)
        #pragma unroll
        for (int j = 0; j < 4; j++)
            wmma::store_matrix_sync(sc + (size_t)(wm * 32 + i * 16) * 128 + wn * 64 + j * 16,
                                    fc[i][j], 128, wmma::mem_row_major);
    __syncthreads();

    // coalesced p store
    float* C = p + ((size_t)b * THW + t0) * HW + q0;
    #pragma unroll
    for (int l = 0; l < 16; l++) {
        int i = tid + l * 256;                   // 0..4095 float4
        int row = i >> 5, col = (i & 31) << 2;
        *(float4*)(C + (size_t)row * HW + col) = *(float4*)(sc + row * 128 + col);
    }

    // fused argmax partial: 2 threads per row (64 q each)
    {
        int row = tid >> 1, h = tid & 1;
        const float* r = sc + row * 128 + h * 64;
        float bv = r[0];
        int bj = 0;
        #pragma unroll 8
        for (int k = 1; k < 64; k++)
            if (r[k] > bv) { bv = r[k]; bj = k; }
        int gq = q0 + h * 64 + bj;
        float ov = __shfl_xor_sync(~0u, bv, 1);
        int   oi = __shfl_xor_sync(~0u, gq, 1);
        if (ov > bv || (ov == bv && oi < gq)) { bv = ov; gq = oi; }
        if (h == 0)
            g_amax[((size_t)b * THW + t0 + row) * 8 + blockIdx.x] =
                make_float2(bv, (float)gq);
    }
}

// reduce 8 tile-partials per row -> gaussian center
__global__ void __launch_bounds__(256) argmax_final()
{
    int r = blockIdx.x * 256 + threadIdx.x;
    if (r >= B_ * THW) return;
    const float2* a = g_amax + (size_t)r * 8;
    float bv = a[0].x;
    int bi = (int)a[0].y;
    #pragma unroll
    for (int k = 1; k < 8; k++) {
        float2 v = a[k];
        if (v.x > bv) { bv = v.x; bi = (int)v.y; }
    }
    g_center[r] = make_float2((float)(bi & 31), (float)(bi >> 5));
}

// ============================================================
// exp + transpose: e^T bf16 hi/lo + partial sums (p preserved)
// ============================================================
__global__ void __launch_bounds__(256) exp_t_kernel(const float* __restrict__ p)
{
    __shared__ float tile[32][129];    // [q][t]
    __shared__ float ssum[8][32];
    const int b = blockIdx.z, t0 = blockIdx.y * 128, q0 = blockIdx.x * 32;
    const int tid = threadIdx.x, tx = tid & 31, ty = tid >> 5;
    const float qx = (float)((q0 + tx) & 31), qy = (float)((q0 + tx) >> 5);
    const float* pc = p + ((size_t)b * THW + t0) * HW + q0 + tx;
    const float2* cen = g_center + (size_t)b * THW + t0;
    float s = 0.f;
    #pragma unroll 4
    for (int r = 0; r < 16; r++) {
        int t = ty * 16 + r;
        float2 c = cen[t];
        float dx = qx - c.x, dy = qy - c.y;
        float v = __expf(pc[(size_t)t * HW] - (dx * dx + dy * dy) * INV2SIG2);
        tile[tx][t] = v;
        s += v;
    }
    ssum[ty][tx] = s;
    __syncthreads();
    if (ty == 0) {
        float a = 0.f;
        #pragma unroll
        for (int k = 0; k < 8; k++) a += ssum[k][tx];
        g_part[((size_t)b * NCHUNK + blockIdx.y) * HW + q0 + tx] = a;
    }
    const int qq = tid >> 3, seg = tid & 7;
    uint32_t hi[8], lo[8];
    #pragma unroll
    for (int k = 0; k < 8; k++) {
        float v0 = tile[qq][seg * 16 + 2 * k];
        float v1 = tile[qq][seg * 16 + 2 * k + 1];
        __nv_bfloat16 h0 = __float2bfloat16(v0), h1 = __float2bfloat16(v1);
        hi[k] = ((uint32_t)*(uint16_t*)&h1 << 16) | *(uint16_t*)&h0;
        __nv_bfloat16 l0 = __float2bfloat16(v0 - __bfloat162float(h0));
        __nv_bfloat16 l1 = __float2bfloat16(v1 - __bfloat162float(h1));
        lo[k] = ((uint32_t)*(uint16_t*)&l1 << 16) | *(uint16_t*)&l0;
    }
    size_t o = ((size_t)b * HW + q0 + qq) * THW + t0 + seg * 16;
    *(uint4*)(g_ehi + o)     = make_uint4(hi[0], hi[1], hi[2], hi[3]);
    *(uint4*)(g_ehi + o + 8) = make_uint4(hi[4], hi[5], hi[6], hi[7]);
    *(uint4*)(g_elo + o)     = make_uint4(lo[0], lo[1], lo[2], lo[3]);
    *(uint4*)(g_elo + o + 8) = make_uint4(lo[4], lo[5], lo[6], lo[7]);
}

__global__ void __launch_bounds__(256) inv_kernel()
{
    int i = blockIdx.x * 256 + threadIdx.x;
    int b = i >> 10, q = i & 1023;
    float s = 0.f;
    #pragma unroll
    for (int c = 0; c < NCHUNK; c++) s += g_part[((size_t)b * NCHUNK + c) * HW + q];
    g_inv[i] = 1.0f / s;
}

// ============================================================
// WMMA bf16 GEMM2 v3: CTA 128x256, 8 warps, warp tile 64x64,
// K-chunk 32, 3-stage cp.async, split-K=2; pass-outer mma order
// ============================================================
#define KP 40
#define A_ROWS 128
#define B_ROWS 256
#define A_TILE_E (A_ROWS * KP)
#define B_TILE_E (B_ROWS * KP)
#define STAGE_E (2 * A_TILE_E + 2 * B_TILE_E)
#define SMEM_DYN (3 * STAGE_E * 2)              // 184320 bytes

__global__ void __launch_bounds__(256) gemm2_wmma()
{
    extern __shared__ __nv_bfloat16 dsm[];
    const int b = blockIdx.z >> 1, half = blockIdx.z & 1;
    const int kbase = half * (THW / 2);
    const int q0 = blockIdx.x * 256, o0 = blockIdx.y * 128;
    const int tid = threadIdx.x, wid = tid >> 5;
    const int wm = wid & 1, wn = wid >> 1;       // 2(o) x 4(q) warps, tile 64x64

    const __nv_bfloat16* Ah = g_mohi + ((size_t)b * DO + o0) * THW + kbase;
    const __nv_bfloat16* Al = g_molo + ((size_t)b * DO + o0) * THW + kbase;
    const __nv_bfloat16* Bh = g_ehi  + ((size_t)b * HW + q0) * THW + kbase;
    const __nv_bfloat16* Bl = g_elo  + ((size_t)b * HW + q0) * THW + kbase;

    const uint32_t sbase = (uint32_t)__cvta_generic_to_shared(dsm);

    auto load_stage = [&](int slot, int kc) {
        uint32_t sb = sbase + (uint32_t)slot * (STAGE_E * 2);
        #pragma unroll
        for (int l = 0; l < 12; l++) {
            int idx = tid + l * 256;
            if (idx < 1024) {
                int limb = idx >> 9, r = (idx >> 2) & 127, ch = idx & 3;
                const __nv_bfloat16* src = (limb ? Al : Ah) + (size_t)r * THW + kc + ch * 8;
                cp16(sb + (uint32_t)limb * (A_TILE_E * 2) + r * (KP * 2) + ch * 16, src);
            } else {
                int idx2 = idx - 1024;
                int limb = idx2 >> 10, r = (idx2 >> 2) & 255, ch = idx2 & 3;
                const __nv_bfloat16* src = (limb ? Bl : Bh) + (size_t)r * THW + kc + ch * 8;
                cp16(sb + (uint32_t)(2 * A_TILE_E + limb * B_TILE_E) * 2
                        + r * (KP * 2) + ch * 16, src);
            }
        }
    };

    wmma::fragment<wmma::accumulator, 16, 16, 16, float> fc[4][4];
    #pragma unroll
    for (int i = 0; i < 4; i++)
        #pragma unroll
        for (int j = 0; j < 4; j++) wmma::fill_fragment(fc[i][j], 0.f);

    const int NC = (THW / 2) / 32;   // 160

    load_stage(0, 0);  CP_COMMIT();
    load_stage(1, 32); CP_COMMIT();

    for (int c = 0; c < NC; c++) {
        CP_WAIT(1);
        __syncthreads();
        if (c + 2 < NC) { load_stage((c + 2) % 3, (c + 2) * 32); CP_COMMIT(); }

        __nv_bfloat16* st  = dsm + (size_t)(c % 3) * STAGE_E;
        __nv_bfloat16* tAh = st;
        __nv_bfloat16* tAl = st + A_TILE_E;
        __nv_bfloat16* tBh = st + 2 * A_TILE_E;
        __nv_bfloat16* tBl = tBh + B_TILE_E;

        #pragma unroll
        for (int kk = 0; kk < 32; kk += 16) {
            wmma::fragment<wmma::matrix_a, 16, 16, 16, __nv_bfloat16, wmma::row_major> fah[4], fal[4];
            #pragma unroll
            for (int i = 0; i < 4; i++) {
                wmma::load_matrix_sync(fah[i], tAh + (wm * 64 + i * 16) * KP + kk, KP);
                wmma::load_matrix_sync(fal[i], tAl + (wm * 64 + i * 16) * KP + kk, KP);
            }
            #pragma unroll
            for (int j = 0; j < 4; j++) {
                wmma::fragment<wmma::matrix_b, 16, 16, 16, __nv_bfloat16, wmma::col_major> fbh, fbl;
                wmma::load_matrix_sync(fbh, tBh + (wn * 64 + j * 16) * KP + kk, KP);
                wmma::load_matrix_sync(fbl, tBl + (wn * 64 + j * 16) * KP + kk, KP);
                // pass-outer ordering: 4 independent mma between same-fc reuse
                #pragma unroll
                for (int i = 0; i < 4; i++)
                    wmma::mma_sync(fc[i][j], fah[i], fbh, fc[i][j]);
                #pragma unroll
                for (int i = 0; i < 4; i++)
                    wmma::mma_sync(fc[i][j], fah[i], fbl, fc[i][j]);
                #pragma unroll
                for (int i = 0; i < 4; i++)
                    wmma::mma_sync(fc[i][j], fal[i], fbh, fc[i][j]);
            }
        }
    }
    CP_WAIT(0);

    float* C = g_cpart + (((size_t)half * B_ + b) * DO + o0 + wm * 64) * HW + q0 + wn * 64;
    #pragma unroll
    for (int i = 0; i < 4; i++)
        #pragma unroll
        for (int j = 0; j < 4; j++)
            wmma::store_matrix_sync(C + (size_t)(i * 16) * HW + j * 16,
                                    fc[i][j], HW, wmma::mem_row_major);
}

// combine split-K halves + apply inv -> out[:, :Do]
__global__ void __launch_bounds__(256) combine_kernel(float* __restrict__ out)
{
    const size_t n4 = (size_t)B_ * DO * HW / 4;
    size_t i = (size_t)blockIdx.x * 256 + threadIdx.x;
    if (i >= n4) return;
    float4 a = ((const float4*)g_cpart)[i];
    float4 c = ((const float4*)g_cpart)[i + n4];
    size_t q4 = i & 255;
    size_t b  = i / ((size_t)DO * HW / 4);
    float4 inv = ((const float4*)g_inv)[b * 256 + q4];
    float4 v = make_float4((a.x + c.x) * inv.x, (a.y + c.y) * inv.y,
                           (a.z + c.z) * inv.z, (a.w + c.w) * inv.w);
    size_t r = i - b * ((size_t)DO * HW / 4);
    ((float4*)out)[b * ((size_t)2 * DO * HW / 4) + r] = v;
}

__global__ void __launch_bounds__(256) copy_qout_kernel(
    const float* __restrict__ q_out, float* __restrict__ out)
{
    const size_t per_b4 = (size_t)DO * HW / 4;
    size_t i = (size_t)blockIdx.x * 256 + threadIdx.x;
    if (i >= (size_t)B_ * per_b4) return;
    size_t b = i / per_b4, r = i - b * per_b4;
    ((float4*)out)[b * 2 * per_b4 + per_b4 + r] = ((const float4*)q_out)[i];
}

// p_w fp32 output from ehi/elo (no exp): transpose [b][q][t] -> [b][t][q], *inv
__global__ void __launch_bounds__(256) pw_t_kernel(float* __restrict__ dst)
{
    __shared__ float tile[32][129];
    __shared__ float sinv[32];
    const int b = blockIdx.z, t0 = blockIdx.y * 128, q0 = blockIdx.x * 32;
    const int tid = threadIdx.x;

    {
        int q = tid >> 3, seg = tid & 7;
        size_t o = ((size_t)b * HW + q0 + q) * THW + t0 + seg * 16;
        uint4 h0 = *(const uint4*)(g_ehi + o);
        uint4 h1 = *(const uint4*)(g_ehi + o + 8);
        uint4 l0 = *(const uint4*)(g_elo + o);
        uint4 l1 = *(const uint4*)(g_elo + o + 8);
        const uint32_t hw_[8] = {h0.x, h0.y, h0.z, h0.w, h1.x, h1.y, h1.z, h1.w};
        const uint32_t lw_[8] = {l0.x, l0.y, l0.z, l0.w, l1.x, l1.y, l1.z, l1.w};
        #pragma unroll
        for (int k = 0; k < 8; k++) {
            __nv_bfloat162 hv = *(const __nv_bfloat162*)&hw_[k];
            __nv_bfloat162 lv = *(const __nv_bfloat162*)&lw_[k];
            tile[q][seg * 16 + 2 * k]     = __bfloat162float(hv.x) + __bfloat162float(lv.x);
            tile[q][seg * 16 + 2 * k + 1] = __bfloat162float(hv.y) + __bfloat162float(lv.y);
        }
    }
    if (tid < 32) sinv[tid] = g_inv[(size_t)b * HW + q0 + tid];
    __syncthreads();

    int t = tid >> 1, qs = (tid & 1) * 16;
    float* d = dst + ((size_t)b * THW + t0 + t) * HW + q0 + qs;
    #pragma unroll
    for (int k = 0; k < 16; k += 4) {
        float4 v = make_float4(tile[qs + k][t]     * sinv[qs + k],
                               tile[qs + k + 1][t] * sinv[qs + k + 1],
                               tile[qs + k + 2][t] * sinv[qs + k + 2],
                               tile[qs + k + 3][t] * sinv[qs + k + 3]);
        *(float4*)(d + k) = v;
    }
}

// ============================================================
extern "C" void kernel_launch(void* const* d_in, const int* in_sizes, int n_in,
                              void* d_out, int out_size)
{
    const float* m_in  = (const float*)d_in[0];
    const float* m_out = (const float*)d_in[1];
    const float* q_in  = (const float*)d_in[2];
    const float* q_out = (const float*)d_in[3];
    float* out = (float*)d_out;

    float* p = nullptr;
    cudaGetSymbolAddress((void**)&p, g_p);
    __nv_bfloat16 *mi0, *mi1, *mi2, *qi0, *qi1, *qi2;
    cudaGetSymbolAddress((void**)&mi0, g_mi0);
    cudaGetSymbolAddress((void**)&mi1, g_mi1);
    cudaGetSymbolAddress((void**)&mi2, g_mi2);
    cudaGetSymbolAddress((void**)&qi0, g_qi0);
    cudaGetSymbolAddress((void**)&qi1, g_qi1);
    cudaGetSymbolAddress((void**)&qi2, g_qi2);

    cudaFuncSetAttribute(gemm1_wmma, cudaFuncAttributeMaxDynamicSharedMemorySize, G1_SMEM);
    cudaFuncSetAttribute(gemm2_wmma, cudaFuncAttributeMaxDynamicSharedMemorySize, SMEM_DYN);

    // 0) split mi (3 limbs), qi*SCALE (3 limbs), mo (2 limbs)
    split3_kernel<<<2048, 256>>>(m_in, mi0, mi1, mi2, (size_t)B_ * DE * THW / 4, 1.0f);
    split3_kernel<<<512, 256>>>(q_in, qi0, qi1, qi2, (size_t)B_ * DE * HW / 4, SCALE);
    split_kernel<<<4096, 256>>>(m_out);

    // 1) p = mi^T (qi*SCALE) via WMMA 3-limb + fused argmax partials
    dim3 g1(HW / 128, THW / 128, B_);   // (8, 80, 4)
    gemm1_wmma<<<g1, 256, G1_SMEM>>>(p);

    // 2) argmax final reduce -> centers
    argmax_final<<<(B_ * THW + 255) / 256, 256>>>();

    // 3) exp + transpose + partial sums
    dim3 g3(HW / 32, THW / 128, B_);
    exp_t_kernel<<<g3, 256>>>(p);

    // 4) inv
    inv_kernel<<<(B_ * HW) / 256, 256>>>();

    // 5) WMMA bf16 GEMM2 v3
    dim3 g4(HW / 256, DO / 128, B_ * 2);   // 128 CTAs
    gemm2_wmma<<<g4, 256, SMEM_DYN>>>();

    // 6) combine halves + normalize -> out[:, :Do]
    combine_kernel<<<(B_ * DO * HW / 4 + 255) / 256, 256>>>(out);

    // 7) out[:, Do:] = q_out
    copy_qout_kernel<<<(B_ * DO * HW / 4 + 255) / 256, 256>>>(q_out, out);

    // 8) optional p_w output (from ehi/elo, no exp)
    const size_t memout = (size_t)B_ * 2 * DO * HW;
    const size_t pw     = (size_t)B_ * THW * HW;
    if ((size_t)out_size >= memout + pw) {
        dim3 g5(HW / 32, THW / 128, B_);
        pw_t_kernel<<<g5, 256>>>(out + memout);
    }
}

// round 13
// speedup vs baseline: 1.4569x; 1.4569x over previous
#include <cuda_runtime.h>
#include <cuda_fp16.h>
#include <mma.h>
#include <cstdint>
#include <math.h>

using namespace nvcuda;

#define B_    4
#define DE    128
#define DO    512
#define THW   10240
#define HW    1024
#define NCHUNK 80
#define SCALE 0.08838834764831845f
#define INV2SIG2 (1.0f/18.0f)

// ---------------- device scratch ----------------
__device__ float  g_p[(size_t)B_ * THW * HW];       // p fp32 (preserved)
__device__ __half g_ehi[(size_t)B_ * HW * THW];     // e^T [b][q][t] fp16 hi
__device__ __half g_elo[(size_t)B_ * HW * THW];     // fp16 lo (pw output only)
__device__ __half g_mohi[(size_t)B_ * DO * THW];
__device__ __half g_molo[(size_t)B_ * DO * THW];
__device__ __half g_mi0[(size_t)B_ * DE * THW];     // mi 2 limbs [b][d][t]
__device__ __half g_mi1[(size_t)B_ * DE * THW];
__device__ __half g_qi0[(size_t)B_ * DE * HW];      // qi*SCALE 2 limbs [b][d][q]
__device__ __half g_qi1[(size_t)B_ * DE * HW];
__device__ float  g_cpart[(size_t)2 * B_ * DO * HW]; // split-K partials
__device__ float2 g_center[B_ * THW];
__device__ float2 g_amax[(size_t)B_ * THW * 8];
__device__ float  g_part[(size_t)B_ * NCHUNK * HW];
__device__ float  g_inv[B_ * HW];

__device__ __forceinline__ void cp16(uint32_t sa, const void* g) {
    asm volatile("cp.async.cg.shared.global [%0], [%1], 16;" :: "r"(sa), "l"(g));
}
#define CP_COMMIT() asm volatile("cp.async.commit_group;" ::: "memory")
#define CP_WAIT(n)  asm volatile("cp.async.wait_group %0;" :: "n"(n) : "memory")

// ============================================================
// split fp32 -> 2 fp16 limbs (optional scale)
// ============================================================
__global__ void __launch_bounds__(256) split2h_kernel(
    const float* __restrict__ in, __half* __restrict__ o0,
    __half* __restrict__ o1, size_t n4, float scale)
{
    const size_t stride = (size_t)gridDim.x * 256;
    for (size_t i = (size_t)blockIdx.x * 256 + threadIdx.x; i < n4; i += stride) {
        float4 v = ((const float4*)in)[i];
        float f[4] = {v.x * scale, v.y * scale, v.z * scale, v.w * scale};
        uint16_t l0[4], l1[4];
        #pragma unroll
        for (int k = 0; k < 4; k++) {
            __half h = __float2half(f[k]);
            __half l = __float2half(f[k] - __half2float(h));
            l0[k] = *(uint16_t*)&h;
            l1[k] = *(uint16_t*)&l;
        }
        ((uint2*)o0)[i] = make_uint2(l0[0] | ((uint32_t)l0[1] << 16), l0[2] | ((uint32_t)l0[3] << 16));
        ((uint2*)o1)[i] = make_uint2(l1[0] | ((uint32_t)l1[1] << 16), l1[2] | ((uint32_t)l1[3] << 16));
    }
}

// ============================================================
// WMMA fp16 GEMM1 (2-limb, 3 passes): p = (mi)^T (qi*SCALE)
// 256 threads / 8 warps (4x2), warp tile 32(t) x 64(q), 2 CTAs/SM
// ============================================================
#define TP 136
#define G1_TILE (32 * TP)
#define G1_STAGE (4 * G1_TILE)
#define G1_SMEM (2 * G1_STAGE * 2)              // 69632 bytes

__global__ void __launch_bounds__(256, 2) gemm1_wmma(float* __restrict__ p)
{
    extern __shared__ __half dsm[];
    const int b = blockIdx.z;
    const int q0 = blockIdx.x * 128, t0 = blockIdx.y * 128;
    const int tid = threadIdx.x, wid = tid >> 5;
    const int wm = wid & 3, wn = wid >> 2;       // warp tile 32(t) x 64(q)

    const __half* A0 = g_mi0 + (size_t)b * DE * THW;
    const __half* A1 = g_mi1 + (size_t)b * DE * THW;
    const __half* B0 = g_qi0 + (size_t)b * DE * HW;
    const __half* B1 = g_qi1 + (size_t)b * DE * HW;

    const uint32_t sbase = (uint32_t)__cvta_generic_to_shared(dsm);

    auto load_stage = [&](int slot, int k0) {
        uint32_t sb = sbase + (uint32_t)slot * (G1_STAGE * 2);
        #pragma unroll
        for (int l = 0; l < 8; l++) {
            int idx = tid + l * 256;             // 0..2047
            int arr = idx >> 9, rem = idx & 511;
            int row = rem >> 4, col = rem & 15;  // row<32 (d), col*8 elems
            const __half* src;
            if (arr < 2) {
                src = (arr == 0 ? A0 : A1) + (size_t)(k0 + row) * THW + t0 + col * 8;
            } else {
                src = (arr == 2 ? B0 : B1) + (size_t)(k0 + row) * HW + q0 + col * 8;
            }
            cp16(sb + (uint32_t)arr * (G1_TILE * 2) + row * (TP * 2) + col * 16, src);
        }
    };

    wmma::fragment<wmma::accumulator, 16, 16, 16, float> fc[2][4];
    #pragma unroll
    for (int i = 0; i < 2; i++)
        #pragma unroll
        for (int j = 0; j < 4; j++) wmma::fill_fragment(fc[i][j], 0.f);

    const int NC = DE / 32;   // 4
    load_stage(0, 0);
    CP_COMMIT();

    for (int c = 0; c < NC; c++) {
        if (c + 1 < NC) { load_stage((c + 1) & 1, (c + 1) * 32); CP_COMMIT(); }
        if (c + 1 < NC) CP_WAIT(1); else CP_WAIT(0);
        __syncthreads();

        __half* st = dsm + (size_t)(c & 1) * G1_STAGE;
        #pragma unroll
        for (int kk = 0; kk < 32; kk += 16) {
            wmma::fragment<wmma::matrix_a, 16, 16, 16, __half, wmma::col_major> fa[2][2];
            wmma::fragment<wmma::matrix_b, 16, 16, 16, __half, wmma::row_major> fb[2][4];
            #pragma unroll
            for (int l = 0; l < 2; l++)
                #pragma unroll
                for (int i = 0; i < 2; i++)
                    wmma::load_matrix_sync(fa[l][i],
                        st + l * G1_TILE + kk * TP + wm * 32 + i * 16, TP);
            #pragma unroll
            for (int l = 0; l < 2; l++)
                #pragma unroll
                for (int j = 0; j < 4; j++)
                    wmma::load_matrix_sync(fb[l][j],
                        st + (2 + l) * G1_TILE + kk * TP + wn * 64 + j * 16, TP);
            // 3 passes: A0B0, A0B1, A1B0
            #pragma unroll
            for (int i = 0; i < 2; i++)
                #pragma unroll
                for (int j = 0; j < 4; j++)
                    wmma::mma_sync(fc[i][j], fa[0][i], fb[0][j], fc[i][j]);
            #pragma unroll
            for (int i = 0; i < 2; i++)
                #pragma unroll
                for (int j = 0; j < 4; j++)
                    wmma::mma_sync(fc[i][j], fa[0][i], fb[1][j], fc[i][j]);
            #pragma unroll
            for (int i = 0; i < 2; i++)
                #pragma unroll
                for (int j = 0; j < 4; j++)
                    wmma::mma_sync(fc[i][j], fa[1][i], fb[0][j], fc[i][j]);
        }
        __syncthreads();
    }

    // epilogue via smem: 128x128 fp32 tile
    float* sc = (float*)dsm;
    #pragma unroll
    for (int i = 0; i < 2; i++)
        #pragma unroll
        for (int j = 0; j < 4; j++)
            wmma::store_matrix_sync(sc + (size_t)(wm * 32 + i * 16) * 128 + wn * 64 + j * 16,
                                    fc[i][j], 128, wmma::mem_row_major);
    __syncthreads();

    // coalesced p store
    float* C = p + ((size_t)b * THW + t0) * HW + q0;
    #pragma unroll
    for (int l = 0; l < 16; l++) {
        int i = tid + l * 256;                   // 0..4095 float4
        int row = i >> 5, col = (i & 31) << 2;
        *(float4*)(C + (size_t)row * HW + col) = *(float4*)(sc + row * 128 + col);
    }

    // fused argmax partial: 2 threads per row (64 q each)
    {
        int row = tid >> 1, h = tid & 1;
        const float* r = sc + row * 128 + h * 64;
        float bv = r[0];
        int bj = 0;
        #pragma unroll 8
        for (int k = 1; k < 64; k++)
            if (r[k] > bv) { bv = r[k]; bj = k; }
        int gq = q0 + h * 64 + bj;
        float ov = __shfl_xor_sync(~0u, bv, 1);
        int   oi = __shfl_xor_sync(~0u, gq, 1);
        if (ov > bv || (ov == bv && oi < gq)) { bv = ov; gq = oi; }
        if (h == 0)
            g_amax[((size_t)b * THW + t0 + row) * 8 + blockIdx.x] =
                make_float2(bv, (float)gq);
    }
}

// reduce 8 tile-partials per row -> gaussian center
__global__ void __launch_bounds__(256) argmax_final()
{
    int r = blockIdx.x * 256 + threadIdx.x;
    if (r >= B_ * THW) return;
    const float2* a = g_amax + (size_t)r * 8;
    float bv = a[0].x;
    int bi = (int)a[0].y;
    #pragma unroll
    for (int k = 1; k < 8; k++) {
        float2 v = a[k];
        if (v.x > bv) { bv = v.x; bi = (int)v.y; }
    }
    g_center[r] = make_float2((float)(bi & 31), (float)(bi >> 5));
}

// ============================================================
// exp + transpose: e^T fp16 hi/lo + partial sums (p preserved)
// ============================================================
__global__ void __launch_bounds__(256) exp_t_kernel(const float* __restrict__ p)
{
    __shared__ float tile[32][129];    // [q][t]
    __shared__ float ssum[8][32];
    const int b = blockIdx.z, t0 = blockIdx.y * 128, q0 = blockIdx.x * 32;
    const int tid = threadIdx.x, tx = tid & 31, ty = tid >> 5;
    const float qx = (float)((q0 + tx) & 31), qy = (float)((q0 + tx) >> 5);
    const float* pc = p + ((size_t)b * THW + t0) * HW + q0 + tx;
    const float2* cen = g_center + (size_t)b * THW + t0;
    float s = 0.f;
    #pragma unroll 4
    for (int r = 0; r < 16; r++) {
        int t = ty * 16 + r;
        float2 c = cen[t];
        float dx = qx - c.x, dy = qy - c.y;
        float v = __expf(pc[(size_t)t * HW] - (dx * dx + dy * dy) * INV2SIG2);
        tile[tx][t] = v;
        s += v;
    }
    ssum[ty][tx] = s;
    __syncthreads();
    if (ty == 0) {
        float a = 0.f;
        #pragma unroll
        for (int k = 0; k < 8; k++) a += ssum[k][tx];
        g_part[((size_t)b * NCHUNK + blockIdx.y) * HW + q0 + tx] = a;
    }
    const int qq = tid >> 3, seg = tid & 7;
    uint32_t hi[8], lo[8];
    #pragma unroll
    for (int k = 0; k < 8; k++) {
        float v0 = tile[qq][seg * 16 + 2 * k];
        float v1 = tile[qq][seg * 16 + 2 * k + 1];
        __half h0 = __float2half(v0), h1 = __float2half(v1);
        hi[k] = ((uint32_t)*(uint16_t*)&h1 << 16) | *(uint16_t*)&h0;
        __half l0 = __float2half(v0 - __half2float(h0));
        __half l1 = __float2half(v1 - __half2float(h1));
        lo[k] = ((uint32_t)*(uint16_t*)&l1 << 16) | *(uint16_t*)&l0;
    }
    size_t o = ((size_t)b * HW + q0 + qq) * THW + t0 + seg * 16;
    *(uint4*)(g_ehi + o)     = make_uint4(hi[0], hi[1], hi[2], hi[3]);
    *(uint4*)(g_ehi + o + 8) = make_uint4(hi[4], hi[5], hi[6], hi[7]);
    *(uint4*)(g_elo + o)     = make_uint4(lo[0], lo[1], lo[2], lo[3]);
    *(uint4*)(g_elo + o + 8) = make_uint4(lo[4], lo[5], lo[6], lo[7]);
}

__global__ void __launch_bounds__(256) inv_kernel()
{
    int i = blockIdx.x * 256 + threadIdx.x;
    int b = i >> 10, q = i & 1023;
    float s = 0.f;
    #pragma unroll
    for (int c = 0; c < NCHUNK; c++) s += g_part[((size_t)b * NCHUNK + c) * HW + q];
    g_inv[i] = 1.0f / s;
}

// ============================================================
// WMMA fp16 GEMM2: D = (mo_hi + mo_lo) . e_hi^T  (2 passes)
// CTA 128x256, 8 warps, warp tile 64x64, K-chunk 32, 3-stage, split-K=2
// ============================================================
#define KP 40
#define A_TILE_E (128 * KP)                     // per limb
#define B_TILE_E (256 * KP)
#define STAGE_E (2 * A_TILE_E + B_TILE_E)       // 20480 elems
#define SMEM_DYN (3 * STAGE_E * 2)              // 122880 bytes

__global__ void __launch_bounds__(256) gemm2_wmma()
{
    extern __shared__ __half dsm[];
    const int b = blockIdx.z >> 1, half_ = blockIdx.z & 1;
    const int kbase = half_ * (THW / 2);
    const int q0 = blockIdx.x * 256, o0 = blockIdx.y * 128;
    const int tid = threadIdx.x, wid = tid >> 5;
    const int wm = wid & 1, wn = wid >> 1;       // 2(o) x 4(q) warps, tile 64x64

    const __half* Ah = g_mohi + ((size_t)b * DO + o0) * THW + kbase;
    const __half* Al = g_molo + ((size_t)b * DO + o0) * THW + kbase;
    const __half* Bh = g_ehi  + ((size_t)b * HW + q0) * THW + kbase;

    const uint32_t sbase = (uint32_t)__cvta_generic_to_shared(dsm);

    auto load_stage = [&](int slot, int kc) {
        uint32_t sb = sbase + (uint32_t)slot * (STAGE_E * 2);
        #pragma unroll
        for (int l = 0; l < 8; l++) {
            int idx = tid + l * 256;             // 0..2047
            if (idx < 1024) {                    // A: 2 limbs x 128 rows x 4 cp16
                int limb = idx >> 9, r = (idx >> 2) & 127, ch = idx & 3;
                const __half* src = (limb ? Al : Ah) + (size_t)r * THW + kc + ch * 8;
                cp16(sb + (uint32_t)limb * (A_TILE_E * 2) + r * (KP * 2) + ch * 16, src);
            } else {                             // B hi: 256 rows x 4 cp16
                int idx2 = idx - 1024;
                int r = idx2 >> 2, ch = idx2 & 3;
                const __half* src = Bh + (size_t)r * THW + kc + ch * 8;
                cp16(sb + (uint32_t)(2 * A_TILE_E) * 2 + r * (KP * 2) + ch * 16, src);
            }
        }
    };

    wmma::fragment<wmma::accumulator, 16, 16, 16, float> fc[4][4];
    #pragma unroll
    for (int i = 0; i < 4; i++)
        #pragma unroll
        for (int j = 0; j < 4; j++) wmma::fill_fragment(fc[i][j], 0.f);

    const int NC = (THW / 2) / 32;   // 160

    load_stage(0, 0);  CP_COMMIT();
    load_stage(1, 32); CP_COMMIT();

    for (int c = 0; c < NC; c++) {
        CP_WAIT(1);
        __syncthreads();
        if (c + 2 < NC) { load_stage((c + 2) % 3, (c + 2) * 32); CP_COMMIT(); }

        __half* st  = dsm + (size_t)(c % 3) * STAGE_E;
        __half* tAh = st;
        __half* tAl = st + A_TILE_E;
        __half* tBh = st + 2 * A_TILE_E;

        #pragma unroll
        for (int kk = 0; kk < 32; kk += 16) {
            wmma::fragment<wmma::matrix_a, 16, 16, 16, __half, wmma::row_major> fah[4], fal[4];
            #pragma unroll
            for (int i = 0; i < 4; i++) {
                wmma::load_matrix_sync(fah[i], tAh + (wm * 64 + i * 16) * KP + kk, KP);
                wmma::load_matrix_sync(fal[i], tAl + (wm * 64 + i * 16) * KP + kk, KP);
            }
            #pragma unroll
            for (int j = 0; j < 4; j++) {
                wmma::fragment<wmma::matrix_b, 16, 16, 16, __half, wmma::col_major> fbh;
                wmma::load_matrix_sync(fbh, tBh + (wn * 64 + j * 16) * KP + kk, KP);
                #pragma unroll
                for (int i = 0; i < 4; i++)
                    wmma::mma_sync(fc[i][j], fah[i], fbh, fc[i][j]);
                #pragma unroll
                for (int i = 0; i < 4; i++)
                    wmma::mma_sync(fc[i][j], fal[i], fbh, fc[i][j]);
            }
        }
    }
    CP_WAIT(0);

    float* C = g_cpart + (((size_t)half_ * B_ + b) * DO + o0 + wm * 64) * HW + q0 + wn * 64;
    #pragma unroll
    for (int i = 0; i < 4; i++)
        #pragma unroll
        for (int j = 0; j < 4; j++)
            wmma::store_matrix_sync(C + (size_t)(i * 16) * HW + j * 16,
                                    fc[i][j], HW, wmma::mem_row_major);
}

// combine split-K halves + apply inv -> out[:, :Do]
__global__ void __launch_bounds__(256) combine_kernel(float* __restrict__ out)
{
    const size_t n4 = (size_t)B_ * DO * HW / 4;
    size_t i = (size_t)blockIdx.x * 256 + threadIdx.x;
    if (i >= n4) return;
    float4 a = ((const float4*)g_cpart)[i];
    float4 c = ((const float4*)g_cpart)[i + n4];
    size_t q4 = i & 255;
    size_t b  = i / ((size_t)DO * HW / 4);
    float4 inv = ((const float4*)g_inv)[b * 256 + q4];
    float4 v = make_float4((a.x + c.x) * inv.x, (a.y + c.y) * inv.y,
                           (a.z + c.z) * inv.z, (a.w + c.w) * inv.w);
    size_t r = i - b * ((size_t)DO * HW / 4);
    ((float4*)out)[b * ((size_t)2 * DO * HW / 4) + r] = v;
}

__global__ void __launch_bounds__(256) copy_qout_kernel(
    const float* __restrict__ q_out, float* __restrict__ out)
{
    const size_t per_b4 = (size_t)DO * HW / 4;
    size_t i = (size_t)blockIdx.x * 256 + threadIdx.x;
    if (i >= (size_t)B_ * per_b4) return;
    size_t b = i / per_b4, r = i - b * per_b4;
    ((float4*)out)[b * 2 * per_b4 + per_b4 + r] = ((const float4*)q_out)[i];
}

// p_w fp32 output from ehi+elo: transpose [b][q][t] -> [b][t][q], *inv
__global__ void __launch_bounds__(256) pw_t_kernel(float* __restrict__ dst)
{
    __shared__ float tile[32][129];
    __shared__ float sinv[32];
    const int b = blockIdx.z, t0 = blockIdx.y * 128, q0 = blockIdx.x * 32;
    const int tid = threadIdx.x;

    {
        int q = tid >> 3, seg = tid & 7;
        size_t o = ((size_t)b * HW + q0 + q) * THW + t0 + seg * 16;
        uint4 h0 = *(const uint4*)(g_ehi + o);
        uint4 h1 = *(const uint4*)(g_ehi + o + 8);
        uint4 l0 = *(const uint4*)(g_elo + o);
        uint4 l1 = *(const uint4*)(g_elo + o + 8);
        const uint32_t hw_[8] = {h0.x, h0.y, h0.z, h0.w, h1.x, h1.y, h1.z, h1.w};
        const uint32_t lw_[8] = {l0.x, l0.y, l0.z, l0.w, l1.x, l1.y, l1.z, l1.w};
        #pragma unroll
        for (int k = 0; k < 8; k++) {
            __half2 hv = *(const __half2*)&hw_[k];
            __half2 lv = *(const __half2*)&lw_[k];
            tile[q][seg * 16 + 2 * k]     = __half2float(hv.x) + __half2float(lv.x);
            tile[q][seg * 16 + 2 * k + 1] = __half2float(hv.y) + __half2float(lv.y);
        }
    }
    if (tid < 32) sinv[tid] = g_inv[(size_t)b * HW + q0 + tid];
    __syncthreads();

    int t = tid >> 1, qs = (tid & 1) * 16;
    float* d = dst + ((size_t)b * THW + t0 + t) * HW + q0 + qs;
    #pragma unroll
    for (int k = 0; k < 16; k += 4) {
        float4 v = make_float4(tile[qs + k][t]     * sinv[qs + k],
                               tile[qs + k + 1][t] * sinv[qs + k + 1],
                               tile[qs + k + 2][t] * sinv[qs + k + 2],
                               tile[qs + k + 3][t] * sinv[qs + k + 3]);
        *(float4*)(d + k) = v;
    }
}

// ============================================================
extern "C" void kernel_launch(void* const* d_in, const int* in_sizes, int n_in,
                              void* d_out, int out_size)
{
    const float* m_in  = (const float*)d_in[0];
    const float* m_out = (const float*)d_in[1];
    const float* q_in  = (const float*)d_in[2];
    const float* q_out = (const float*)d_in[3];
    float* out = (float*)d_out;

    float* p = nullptr;
    cudaGetSymbolAddress((void**)&p, g_p);
    __half *mi0, *mi1, *qi0, *qi1, *moh, *mol;
    cudaGetSymbolAddress((void**)&mi0, g_mi0);
    cudaGetSymbolAddress((void**)&mi1, g_mi1);
    cudaGetSymbolAddress((void**)&qi0, g_qi0);
    cudaGetSymbolAddress((void**)&qi1, g_qi1);
    cudaGetSymbolAddress((void**)&moh, g_mohi);
    cudaGetSymbolAddress((void**)&mol, g_molo);

    cudaFuncSetAttribute(gemm1_wmma, cudaFuncAttributeMaxDynamicSharedMemorySize, G1_SMEM);
    cudaFuncSetAttribute(gemm2_wmma, cudaFuncAttributeMaxDynamicSharedMemorySize, SMEM_DYN);

    // 0) split mi, qi*SCALE, mo into fp16 2-limb
    split2h_kernel<<<2048, 256>>>(m_in, mi0, mi1, (size_t)B_ * DE * THW / 4, 1.0f);
    split2h_kernel<<<512, 256>>>(q_in, qi0, qi1, (size_t)B_ * DE * HW / 4, SCALE);
    split2h_kernel<<<4096, 256>>>(m_out, moh, mol, (size_t)B_ * DO * THW / 4, 1.0f);

    // 1) p = mi^T (qi*SCALE) via WMMA fp16 2-limb + fused argmax partials
    dim3 g1(HW / 128, THW / 128, B_);   // (8, 80, 4)
    gemm1_wmma<<<g1, 256, G1_SMEM>>>(p);

    // 2) argmax final reduce -> centers
    argmax_final<<<(B_ * THW + 255) / 256, 256>>>();

    // 3) exp + transpose + partial sums
    dim3 g3(HW / 32, THW / 128, B_);
    exp_t_kernel<<<g3, 256>>>(p);

    // 4) inv
    inv_kernel<<<(B_ * HW) / 256, 256>>>();

    // 5) WMMA fp16 GEMM2 (2 passes, B hi-only), split-K=2
    dim3 g4(HW / 256, DO / 128, B_ * 2);   // 128 CTAs
    gemm2_wmma<<<g4, 256, SMEM_DYN>>>();

    // 6) combine halves + normalize -> out[:, :Do]
    combine_kernel<<<(B_ * DO * HW / 4 + 255) / 256, 256>>>(out);

    // 7) out[:, Do:] = q_out
    copy_qout_kernel<<<(B_ * DO * HW / 4 + 255) / 256, 256>>>(q_out, out);

    // 8) optional p_w output (hi+lo, fp32-accurate)
    const size_t memout = (size_t)B_ * 2 * DO * HW;
    const size_t pw     = (size_t)B_ * THW * HW;
    if ((size_t)out_size >= memout + pw) {
        dim3 g5(HW / 32, THW / 128, B_);
        pw_t_kernel<<<g5, 256>>>(out + memout);
    }
}

// round 14
// speedup vs baseline: 1.8155x; 1.2462x over previous
#include <cuda_runtime.h>
#include <cuda_fp16.h>
#include <mma.h>
#include <cstdint>
#include <math.h>

using namespace nvcuda;

#define B_    4
#define DE    128
#define DO    512
#define THW   10240
#define HW    1024
#define NCHUNK 80
#define SCALE 0.08838834764831845f
#define INV2SIG2 (1.0f/18.0f)

// ---------------- device scratch ----------------
__device__ float  g_p[(size_t)B_ * THW * HW];       // p fp32 (preserved)
__device__ __half g_ehi[(size_t)B_ * HW * THW];     // e^T [b][q][t] fp16 hi
__device__ __half g_elo[(size_t)B_ * HW * THW];     // fp16 lo (pw output only)
__device__ __half g_mohi[(size_t)B_ * DO * THW];    // mo fp16 hi (only limb used)
__device__ __half g_mi0[(size_t)B_ * DE * THW];     // mi 2 limbs [b][d][t]
__device__ __half g_mi1[(size_t)B_ * DE * THW];
__device__ __half g_qi0[(size_t)B_ * DE * HW];      // qi*SCALE 2 limbs [b][d][q]
__device__ __half g_qi1[(size_t)B_ * DE * HW];
__device__ float  g_cpart[(size_t)2 * B_ * DO * HW]; // split-K partials
__device__ float2 g_center[B_ * THW];
__device__ float2 g_amax[(size_t)B_ * THW * 8];
__device__ float  g_part[(size_t)B_ * NCHUNK * HW];
__device__ float  g_inv[B_ * HW];

__device__ __forceinline__ void cp16(uint32_t sa, const void* g) {
    asm volatile("cp.async.cg.shared.global [%0], [%1], 16;" :: "r"(sa), "l"(g));
}
#define CP_COMMIT() asm volatile("cp.async.commit_group;" ::: "memory")
#define CP_WAIT(n)  asm volatile("cp.async.wait_group %0;" :: "n"(n) : "memory")

// ============================================================
// split fp32 -> 2 fp16 limbs (optional scale)
// ============================================================
__global__ void __launch_bounds__(256) split2h_kernel(
    const float* __restrict__ in, __half* __restrict__ o0,
    __half* __restrict__ o1, size_t n4, float scale)
{
    const size_t stride = (size_t)gridDim.x * 256;
    for (size_t i = (size_t)blockIdx.x * 256 + threadIdx.x; i < n4; i += stride) {
        float4 v = ((const float4*)in)[i];
        float f[4] = {v.x * scale, v.y * scale, v.z * scale, v.w * scale};
        uint16_t l0[4], l1[4];
        #pragma unroll
        for (int k = 0; k < 4; k++) {
            __half h = __float2half(f[k]);
            __half l = __float2half(f[k] - __half2float(h));
            l0[k] = *(uint16_t*)&h;
            l1[k] = *(uint16_t*)&l;
        }
        ((uint2*)o0)[i] = make_uint2(l0[0] | ((uint32_t)l0[1] << 16), l0[2] | ((uint32_t)l0[3] << 16));
        ((uint2*)o1)[i] = make_uint2(l1[0] | ((uint32_t)l1[1] << 16), l1[2] | ((uint32_t)l1[3] << 16));
    }
}

// split fp32 -> fp16 hi only
__global__ void __launch_bounds__(256) split1h_kernel(
    const float* __restrict__ in, __half* __restrict__ o0, size_t n4)
{
    const size_t stride = (size_t)gridDim.x * 256;
    for (size_t i = (size_t)blockIdx.x * 256 + threadIdx.x; i < n4; i += stride) {
        float4 v = ((const float4*)in)[i];
        __half h0 = __float2half(v.x), h1 = __float2half(v.y);
        __half h2 = __float2half(v.z), h3 = __float2half(v.w);
        uint16_t u0 = *(uint16_t*)&h0, u1 = *(uint16_t*)&h1;
        uint16_t u2 = *(uint16_t*)&h2, u3 = *(uint16_t*)&h3;
        ((uint2*)o0)[i] = make_uint2(u0 | ((uint32_t)u1 << 16), u2 | ((uint32_t)u3 << 16));
    }
}

// ============================================================
// WMMA fp16 GEMM1 (2-limb, 3 passes): p = (mi)^T (qi*SCALE)
// 128 threads / 4 warps (2x2), warp tile 64(t) x 64(q), 2 CTAs/SM
// mma:frag-load ratio = 48:16 = 3.0
// ============================================================
#define TP 136
#define G1_TILE (32 * TP)
#define G1_STAGE (4 * G1_TILE)
#define G1_SMEM (2 * G1_STAGE * 2)              // 69632 bytes

__global__ void __launch_bounds__(128, 2) gemm1_wmma(float* __restrict__ p)
{
    extern __shared__ __half dsm[];
    const int b = blockIdx.z;
    const int q0 = blockIdx.x * 128, t0 = blockIdx.y * 128;
    const int tid = threadIdx.x, wid = tid >> 5;
    const int wm = wid & 1, wn = wid >> 1;       // 2x2 warps, tile 64(t) x 64(q)

    const __half* A0 = g_mi0 + (size_t)b * DE * THW;
    const __half* A1 = g_mi1 + (size_t)b * DE * THW;
    const __half* B0 = g_qi0 + (size_t)b * DE * HW;
    const __half* B1 = g_qi1 + (size_t)b * DE * HW;

    const uint32_t sbase = (uint32_t)__cvta_generic_to_shared(dsm);

    auto load_stage = [&](int slot, int k0) {
        uint32_t sb = sbase + (uint32_t)slot * (G1_STAGE * 2);
        #pragma unroll
        for (int l = 0; l < 16; l++) {
            int idx = tid + l * 128;             // 0..2047
            int arr = idx >> 9, rem = idx & 511;
            int row = rem >> 4, col = rem & 15;  // row<32 (d), col*8 elems
            const __half* src;
            if (arr < 2) {
                src = (arr == 0 ? A0 : A1) + (size_t)(k0 + row) * THW + t0 + col * 8;
            } else {
                src = (arr == 2 ? B0 : B1) + (size_t)(k0 + row) * HW + q0 + col * 8;
            }
            cp16(sb + (uint32_t)arr * (G1_TILE * 2) + row * (TP * 2) + col * 16, src);
        }
    };

    wmma::fragment<wmma::accumulator, 16, 16, 16, float> fc[4][4];
    #pragma unroll
    for (int i = 0; i < 4; i++)
        #pragma unroll
        for (int j = 0; j < 4; j++) wmma::fill_fragment(fc[i][j], 0.f);

    const int NC = DE / 32;   // 4
    load_stage(0, 0);
    CP_COMMIT();

    for (int c = 0; c < NC; c++) {
        if (c + 1 < NC) { load_stage((c + 1) & 1, (c + 1) * 32); CP_COMMIT(); }
        if (c + 1 < NC) CP_WAIT(1); else CP_WAIT(0);
        __syncthreads();

        __half* st = dsm + (size_t)(c & 1) * G1_STAGE;
        #pragma unroll
        for (int kk = 0; kk < 32; kk += 16) {
            wmma::fragment<wmma::matrix_a, 16, 16, 16, __half, wmma::col_major> fa[2][4];
            wmma::fragment<wmma::matrix_b, 16, 16, 16, __half, wmma::row_major> fb[2][4];
            #pragma unroll
            for (int l = 0; l < 2; l++)
                #pragma unroll
                for (int i = 0; i < 4; i++)
                    wmma::load_matrix_sync(fa[l][i],
                        st + l * G1_TILE + kk * TP + wm * 64 + i * 16, TP);
            #pragma unroll
            for (int l = 0; l < 2; l++)
                #pragma unroll
                for (int j = 0; j < 4; j++)
                    wmma::load_matrix_sync(fb[l][j],
                        st + (2 + l) * G1_TILE + kk * TP + wn * 64 + j * 16, TP);
            // 3 passes: A0B0, A0B1, A1B0 (16 indep mma per pass)
            #pragma unroll
            for (int i = 0; i < 4; i++)
                #pragma unroll
                for (int j = 0; j < 4; j++)
                    wmma::mma_sync(fc[i][j], fa[0][i], fb[0][j], fc[i][j]);
            #pragma unroll
            for (int i = 0; i < 4; i++)
                #pragma unroll
                for (int j = 0; j < 4; j++)
                    wmma::mma_sync(fc[i][j], fa[0][i], fb[1][j], fc[i][j]);
            #pragma unroll
            for (int i = 0; i < 4; i++)
                #pragma unroll
                for (int j = 0; j < 4; j++)
                    wmma::mma_sync(fc[i][j], fa[1][i], fb[0][j], fc[i][j]);
        }
        __syncthreads();
    }

    // epilogue via smem: 128x128 fp32 tile (64KB, fits in 69.6KB)
    float* sc = (float*)dsm;
    #pragma unroll
    for (int i = 0; i < 4; i++)
        #pragma unroll
        for (int j = 0; j < 4; j++)
            wmma::store_matrix_sync(sc + (size_t)(wm * 64 + i * 16) * 128 + wn * 64 + j * 16,
                                    fc[i][j], 128, wmma::mem_row_major);
    __syncthreads();

    // coalesced p store
    float* C = p + ((size_t)b * THW + t0) * HW + q0;
    #pragma unroll
    for (int l = 0; l < 32; l++) {
        int i = tid + l * 128;                   // 0..4095 float4
        int row = i >> 5, col = (i & 31) << 2;
        *(float4*)(C + (size_t)row * HW + col) = *(float4*)(sc + row * 128 + col);
    }

    // fused argmax partial: 1 thread per row (128 q each)
    {
        int row = tid;
        const float* r = sc + row * 128;
        float bv = r[0];
        int bj = 0;
        #pragma unroll 8
        for (int k = 1; k < 128; k++)
            if (r[k] > bv) { bv = r[k]; bj = k; }
        g_amax[((size_t)b * THW + t0 + row) * 8 + blockIdx.x] =
            make_float2(bv, (float)(q0 + bj));
    }
}

// reduce 8 tile-partials per row -> gaussian center
__global__ void __launch_bounds__(256) argmax_final()
{
    int r = blockIdx.x * 256 + threadIdx.x;
    if (r >= B_ * THW) return;
    const float2* a = g_amax + (size_t)r * 8;
    float bv = a[0].x;
    int bi = (int)a[0].y;
    #pragma unroll
    for (int k = 1; k < 8; k++) {
        float2 v = a[k];
        if (v.x > bv) { bv = v.x; bi = (int)v.y; }
    }
    g_center[r] = make_float2((float)(bi & 31), (float)(bi >> 5));
}

// ============================================================
// exp + transpose: e^T fp16 hi/lo + partial sums (p preserved)
// ============================================================
__global__ void __launch_bounds__(256) exp_t_kernel(const float* __restrict__ p)
{
    __shared__ float tile[32][129];    // [q][t]
    __shared__ float ssum[8][32];
    const int b = blockIdx.z, t0 = blockIdx.y * 128, q0 = blockIdx.x * 32;
    const int tid = threadIdx.x, tx = tid & 31, ty = tid >> 5;
    const float qx = (float)((q0 + tx) & 31), qy = (float)((q0 + tx) >> 5);
    const float* pc = p + ((size_t)b * THW + t0) * HW + q0 + tx;
    const float2* cen = g_center + (size_t)b * THW + t0;
    float s = 0.f;
    #pragma unroll 4
    for (int r = 0; r < 16; r++) {
        int t = ty * 16 + r;
        float2 c = cen[t];
        float dx = qx - c.x, dy = qy - c.y;
        float v = __expf(pc[(size_t)t * HW] - (dx * dx + dy * dy) * INV2SIG2);
        tile[tx][t] = v;
        s += v;
    }
    ssum[ty][tx] = s;
    __syncthreads();
    if (ty == 0) {
        float a = 0.f;
        #pragma unroll
        for (int k = 0; k < 8; k++) a += ssum[k][tx];
        g_part[((size_t)b * NCHUNK + blockIdx.y) * HW + q0 + tx] = a;
    }
    const int qq = tid >> 3, seg = tid & 7;
    uint32_t hi[8], lo[8];
    #pragma unroll
    for (int k = 0; k < 8; k++) {
        float v0 = tile[qq][seg * 16 + 2 * k];
        float v1 = tile[qq][seg * 16 + 2 * k + 1];
        __half h0 = __float2half(v0), h1 = __float2half(v1);
        hi[k] = ((uint32_t)*(uint16_t*)&h1 << 16) | *(uint16_t*)&h0;
        __half l0 = __float2half(v0 - __half2float(h0));
        __half l1 = __float2half(v1 - __half2float(h1));
        lo[k] = ((uint32_t)*(uint16_t*)&l1 << 16) | *(uint16_t*)&l0;
    }
    size_t o = ((size_t)b * HW + q0 + qq) * THW + t0 + seg * 16;
    *(uint4*)(g_ehi + o)     = make_uint4(hi[0], hi[1], hi[2], hi[3]);
    *(uint4*)(g_ehi + o + 8) = make_uint4(hi[4], hi[5], hi[6], hi[7]);
    *(uint4*)(g_elo + o)     = make_uint4(lo[0], lo[1], lo[2], lo[3]);
    *(uint4*)(g_elo + o + 8) = make_uint4(lo[4], lo[5], lo[6], lo[7]);
}

__global__ void __launch_bounds__(256) inv_kernel()
{
    int i = blockIdx.x * 256 + threadIdx.x;
    int b = i >> 10, q = i & 1023;
    float s = 0.f;
    #pragma unroll
    for (int c = 0; c < NCHUNK; c++) s += g_part[((size_t)b * NCHUNK + c) * HW + q];
    g_inv[i] = 1.0f / s;
}

// ============================================================
// WMMA fp16 GEMM2: D = mo_hi . e_hi^T  (1 pass)
// CTA 128x256, 8 warps, warp tile 64x64, K-chunk 32, 3-stage, split-K=2
// ============================================================
#define KP 40
#define A_TILE_E (128 * KP)
#define B_TILE_E (256 * KP)
#define STAGE_E (A_TILE_E + B_TILE_E)           // 15360 elems
#define SMEM_DYN (3 * STAGE_E * 2)              // 92160 bytes

__global__ void __launch_bounds__(256) gemm2_wmma()
{
    extern __shared__ __half dsm[];
    const int b = blockIdx.z >> 1, half_ = blockIdx.z & 1;
    const int kbase = half_ * (THW / 2);
    const int q0 = blockIdx.x * 256, o0 = blockIdx.y * 128;
    const int tid = threadIdx.x, wid = tid >> 5;
    const int wm = wid & 1, wn = wid >> 1;       // 2(o) x 4(q) warps, tile 64x64

    const __half* Ah = g_mohi + ((size_t)b * DO + o0) * THW + kbase;
    const __half* Bh = g_ehi  + ((size_t)b * HW + q0) * THW + kbase;

    const uint32_t sbase = (uint32_t)__cvta_generic_to_shared(dsm);

    auto load_stage = [&](int slot, int kc) {
        uint32_t sb = sbase + (uint32_t)slot * (STAGE_E * 2);
        #pragma unroll
        for (int l = 0; l < 6; l++) {
            int idx = tid + l * 256;             // 0..1535
            if (idx < 512) {                     // A hi: 128 rows x 4 cp16
                int r = idx >> 2, ch = idx & 3;
                cp16(sb + r * (KP * 2) + ch * 16, Ah + (size_t)r * THW + kc + ch * 8);
            } else {                             // B hi: 256 rows x 4 cp16
                int idx2 = idx - 512;
                int r = idx2 >> 2, ch = idx2 & 3;
                cp16(sb + (uint32_t)A_TILE_E * 2 + r * (KP * 2) + ch * 16,
                     Bh + (size_t)r * THW + kc + ch * 8);
            }
        }
    };

    wmma::fragment<wmma::accumulator, 16, 16, 16, float> fc[4][4];
    #pragma unroll
    for (int i = 0; i < 4; i++)
        #pragma unroll
        for (int j = 0; j < 4; j++) wmma::fill_fragment(fc[i][j], 0.f);

    const int NC = (THW / 2) / 32;   // 160

    load_stage(0, 0);  CP_COMMIT();
    load_stage(1, 32); CP_COMMIT();

    for (int c = 0; c < NC; c++) {
        CP_WAIT(1);
        __syncthreads();
        if (c + 2 < NC) { load_stage((c + 2) % 3, (c + 2) * 32); CP_COMMIT(); }

        __half* st  = dsm + (size_t)(c % 3) * STAGE_E;
        __half* tAh = st;
        __half* tBh = st + A_TILE_E;

        #pragma unroll
        for (int kk = 0; kk < 32; kk += 16) {
            wmma::fragment<wmma::matrix_a, 16, 16, 16, __half, wmma::row_major> fah[4];
            #pragma unroll
            for (int i = 0; i < 4; i++)
                wmma::load_matrix_sync(fah[i], tAh + (wm * 64 + i * 16) * KP + kk, KP);
            #pragma unroll
            for (int j = 0; j < 4; j++) {
                wmma::fragment<wmma::matrix_b, 16, 16, 16, __half, wmma::col_major> fbh;
                wmma::load_matrix_sync(fbh, tBh + (wn * 64 + j * 16) * KP + kk, KP);
                #pragma unroll
                for (int i = 0; i < 4; i++)
                    wmma::mma_sync(fc[i][j], fah[i], fbh, fc[i][j]);
            }
        }
    }
    CP_WAIT(0);

    float* C = g_cpart + (((size_t)half_ * B_ + b) * DO + o0 + wm * 64) * HW + q0 + wn * 64;
    #pragma unroll
    for (int i = 0; i < 4; i++)
        #pragma unroll
        for (int j = 0; j < 4; j++)
            wmma::store_matrix_sync(C + (size_t)(i * 16) * HW + j * 16,
                                    fc[i][j], HW, wmma::mem_row_major);
}

// combine split-K halves + apply inv -> out[:, :Do]
__global__ void __launch_bounds__(256) combine_kernel(float* __restrict__ out)
{
    const size_t n4 = (size_t)B_ * DO * HW / 4;
    size_t i = (size_t)blockIdx.x * 256 + threadIdx.x;
    if (i >= n4) return;
    float4 a = ((const float4*)g_cpart)[i];
    float4 c = ((const float4*)g_cpart)[i + n4];
    size_t q4 = i & 255;
    size_t b  = i / ((size_t)DO * HW / 4);
    float4 inv = ((const float4*)g_inv)[b * 256 + q4];
    float4 v = make_float4((a.x + c.x) * inv.x, (a.y + c.y) * inv.y,
                           (a.z + c.z) * inv.z, (a.w + c.w) * inv.w);
    size_t r = i - b * ((size_t)DO * HW / 4);
    ((float4*)out)[b * ((size_t)2 * DO * HW / 4) + r] = v;
}

__global__ void __launch_bounds__(256) copy_qout_kernel(
    const float* __restrict__ q_out, float* __restrict__ out)
{
    const size_t per_b4 = (size_t)DO * HW / 4;
    size_t i = (size_t)blockIdx.x * 256 + threadIdx.x;
    if (i >= (size_t)B_ * per_b4) return;
    size_t b = i / per_b4, r = i - b * per_b4;
    ((float4*)out)[b * 2 * per_b4 + per_b4 + r] = ((const float4*)q_out)[i];
}

// p_w fp32 output from ehi+elo: transpose [b][q][t] -> [b][t][q], *inv
__global__ void __launch_bounds__(256) pw_t_kernel(float* __restrict__ dst)
{
    __shared__ float tile[32][129];
    __shared__ float sinv[32];
    const int b = blockIdx.z, t0 = blockIdx.y * 128, q0 = blockIdx.x * 32;
    const int tid = threadIdx.x;

    {
        int q = tid >> 3, seg = tid & 7;
        size_t o = ((size_t)b * HW + q0 + q) * THW + t0 + seg * 16;
        uint4 h0 = *(const uint4*)(g_ehi + o);
        uint4 h1 = *(const uint4*)(g_ehi + o + 8);
        uint4 l0 = *(const uint4*)(g_elo + o);
        uint4 l1 = *(const uint4*)(g_elo + o + 8);
        const uint32_t hw_[8] = {h0.x, h0.y, h0.z, h0.w, h1.x, h1.y, h1.z, h1.w};
        const uint32_t lw_[8] = {l0.x, l0.y, l0.z, l0.w, l1.x, l1.y, l1.z, l1.w};
        #pragma unroll
        for (int k = 0; k < 8; k++) {
            __half2 hv = *(const __half2*)&hw_[k];
            __half2 lv = *(const __half2*)&lw_[k];
            tile[q][seg * 16 + 2 * k]     = __half2float(hv.x) + __half2float(lv.x);
            tile[q][seg * 16 + 2 * k + 1] = __half2float(hv.y) + __half2float(lv.y);
        }
    }
    if (tid < 32) sinv[tid] = g_inv[(size_t)b * HW + q0 + tid];
    __syncthreads();

    int t = tid >> 1, qs = (tid & 1) * 16;
    float* d = dst + ((size_t)b * THW + t0 + t) * HW + q0 + qs;
    #pragma unroll
    for (int k = 0; k < 16; k += 4) {
        float4 v = make_float4(tile[qs + k][t]     * sinv[qs + k],
                               tile[qs + k + 1][t] * sinv[qs + k + 1],
                               tile[qs + k + 2][t] * sinv[qs + k + 2],
                               tile[qs + k + 3][t] * sinv[qs + k + 3]);
        *(float4*)(d + k) = v;
    }
}

// ============================================================
extern "C" void kernel_launch(void* const* d_in, const int* in_sizes, int n_in,
                              void* d_out, int out_size)
{
    const float* m_in  = (const float*)d_in[0];
    const float* m_out = (const float*)d_in[1];
    const float* q_in  = (const float*)d_in[2];
    const float* q_out = (const float*)d_in[3];
    float* out = (float*)d_out;

    float* p = nullptr;
    cudaGetSymbolAddress((void**)&p, g_p);
    __half *mi0, *mi1, *qi0, *qi1, *moh;
    cudaGetSymbolAddress((void**)&mi0, g_mi0);
    cudaGetSymbolAddress((void**)&mi1, g_mi1);
    cudaGetSymbolAddress((void**)&qi0, g_qi0);
    cudaGetSymbolAddress((void**)&qi1, g_qi1);
    cudaGetSymbolAddress((void**)&moh, g_mohi);

    cudaFuncSetAttribute(gemm1_wmma, cudaFuncAttributeMaxDynamicSharedMemorySize, G1_SMEM);
    cudaFuncSetAttribute(gemm2_wmma, cudaFuncAttributeMaxDynamicSharedMemorySize, SMEM_DYN);

    // 0) split mi, qi*SCALE into fp16 2-limb; mo hi-only
    split2h_kernel<<<2048, 256>>>(m_in, mi0, mi1, (size_t)B_ * DE * THW / 4, 1.0f);
    split2h_kernel<<<512, 256>>>(q_in, qi0, qi1, (size_t)B_ * DE * HW / 4, SCALE);
    split1h_kernel<<<2048, 256>>>(m_out, moh, (size_t)B_ * DO * THW / 4);

    // 1) p = mi^T (qi*SCALE) via WMMA fp16 2-limb, 64x64 warp tiles
    dim3 g1(HW / 128, THW / 128, B_);   // (8, 80, 4)
    gemm1_wmma<<<g1, 128, G1_SMEM>>>(p);

    // 2) argmax final reduce -> centers
    argmax_final<<<(B_ * THW + 255) / 256, 256>>>();

    // 3) exp + transpose + partial sums
    dim3 g3(HW / 32, THW / 128, B_);
    exp_t_kernel<<<g3, 256>>>(p);

    // 4) inv
    inv_kernel<<<(B_ * HW) / 256, 256>>>();

    // 5) WMMA fp16 GEMM2 (1 pass), split-K=2
    dim3 g4(HW / 256, DO / 128, B_ * 2);   // 128 CTAs
    gemm2_wmma<<<g4, 256, SMEM_DYN>>>();

    // 6) combine halves + normalize -> out[:, :Do]
    combine_kernel<<<(B_ * DO * HW / 4 + 255) / 256, 256>>>(out);

    // 7) out[:, Do:] = q_out
    copy_qout_kernel<<<(B_ * DO * HW / 4 + 255) / 256, 256>>>(q_out, out);

    // 8) optional p_w output (hi+lo, fp32-accurate)
    const size_t memout = (size_t)B_ * 2 * DO * HW;
    const size_t pw     = (size_t)B_ * THW * HW;
    if ((size_t)out_size >= memout + pw) {
        dim3 g5(HW / 32, THW / 128, B_);
        pw_t_kernel<<<g5, 256>>>(out + memout);
    }
}

// round 15
// speedup vs baseline: 2.0894x; 1.1509x over previous
#include <cuda_runtime.h>
#include <cuda_fp16.h>
#include <mma.h>
#include <cstdint>
#include <math.h>

using namespace nvcuda;

#define B_    4
#define DE    128
#define DO    512
#define THW   10240
#define HW    1024
#define NCHUNK 80
#define SCALE 0.08838834764831845f
#define INV2SIG2 (1.0f/18.0f)

// ---------------- device scratch ----------------
__device__ float  g_p[(size_t)B_ * THW * HW];       // p fp32 (preserved)
__device__ __half g_ehi[(size_t)B_ * HW * THW];     // e^T [b][q][t] fp16 hi
__device__ __half g_mohi[(size_t)B_ * DO * THW];    // mo fp16 hi
__device__ __half g_mi0[(size_t)B_ * DE * THW];     // mi 2 limbs [b][d][t]
__device__ __half g_mi1[(size_t)B_ * DE * THW];
__device__ __half g_qi0[(size_t)B_ * DE * HW];      // qi*SCALE 2 limbs [b][d][q]
__device__ __half g_qi1[(size_t)B_ * DE * HW];
__device__ float  g_cpart[(size_t)2 * B_ * DO * HW]; // split-K partials
__device__ float2 g_center[B_ * THW];
__device__ float2 g_amax[(size_t)B_ * THW * 8];
__device__ float  g_part[(size_t)B_ * NCHUNK * HW];
__device__ float  g_inv[B_ * HW];

__device__ __forceinline__ void cp16(uint32_t sa, const void* g) {
    asm volatile("cp.async.cg.shared.global [%0], [%1], 16;" :: "r"(sa), "l"(g));
}
#define CP_COMMIT() asm volatile("cp.async.commit_group;" ::: "memory")
#define CP_WAIT(n)  asm volatile("cp.async.wait_group %0;" :: "n"(n) : "memory")

// ============================================================
// split fp32 -> 2 fp16 limbs (optional scale)
// ============================================================
__global__ void __launch_bounds__(256) split2h_kernel(
    const float* __restrict__ in, __half* __restrict__ o0,
    __half* __restrict__ o1, size_t n4, float scale)
{
    const size_t stride = (size_t)gridDim.x * 256;
    for (size_t i = (size_t)blockIdx.x * 256 + threadIdx.x; i < n4; i += stride) {
        float4 v = ((const float4*)in)[i];
        float f[4] = {v.x * scale, v.y * scale, v.z * scale, v.w * scale};
        uint16_t l0[4], l1[4];
        #pragma unroll
        for (int k = 0; k < 4; k++) {
            __half h = __float2half(f[k]);
            __half l = __float2half(f[k] - __half2float(h));
            l0[k] = *(uint16_t*)&h;
            l1[k] = *(uint16_t*)&l;
        }
        ((uint2*)o0)[i] = make_uint2(l0[0] | ((uint32_t)l0[1] << 16), l0[2] | ((uint32_t)l0[3] << 16));
        ((uint2*)o1)[i] = make_uint2(l1[0] | ((uint32_t)l1[1] << 16), l1[2] | ((uint32_t)l1[3] << 16));
    }
}

// split fp32 -> fp16 hi only
__global__ void __launch_bounds__(256) split1h_kernel(
    const float* __restrict__ in, __half* __restrict__ o0, size_t n4)
{
    const size_t stride = (size_t)gridDim.x * 256;
    for (size_t i = (size_t)blockIdx.x * 256 + threadIdx.x; i < n4; i += stride) {
        float4 v = ((const float4*)in)[i];
        __half h0 = __float2half(v.x), h1 = __float2half(v.y);
        __half h2 = __float2half(v.z), h3 = __float2half(v.w);
        uint16_t u0 = *(uint16_t*)&h0, u1 = *(uint16_t*)&h1;
        uint16_t u2 = *(uint16_t*)&h2, u3 = *(uint16_t*)&h3;
        ((uint2*)o0)[i] = make_uint2(u0 | ((uint32_t)u1 << 16), u2 | ((uint32_t)u3 << 16));
    }
}

// ============================================================
// WMMA fp16 GEMM1 (2-limb, 3 passes): p = (mi)^T (qi*SCALE)
// 128 threads / 4 warps (2x2), warp tile 64(t) x 64(q), 2 CTAs/SM
// ============================================================
#define TP 136
#define G1_TILE (32 * TP)
#define G1_STAGE (4 * G1_TILE)
#define G1_SMEM (2 * G1_STAGE * 2)              // 69632 bytes

__global__ void __launch_bounds__(128, 2) gemm1_wmma(float* __restrict__ p)
{
    extern __shared__ __half dsm[];
    const int b = blockIdx.z;
    const int q0 = blockIdx.x * 128, t0 = blockIdx.y * 128;
    const int tid = threadIdx.x, wid = tid >> 5;
    const int wm = wid & 1, wn = wid >> 1;       // 2x2 warps, tile 64(t) x 64(q)

    const __half* A0 = g_mi0 + (size_t)b * DE * THW;
    const __half* A1 = g_mi1 + (size_t)b * DE * THW;
    const __half* B0 = g_qi0 + (size_t)b * DE * HW;
    const __half* B1 = g_qi1 + (size_t)b * DE * HW;

    const uint32_t sbase = (uint32_t)__cvta_generic_to_shared(dsm);

    auto load_stage = [&](int slot, int k0) {
        uint32_t sb = sbase + (uint32_t)slot * (G1_STAGE * 2);
        #pragma unroll
        for (int l = 0; l < 16; l++) {
            int idx = tid + l * 128;             // 0..2047
            int arr = idx >> 9, rem = idx & 511;
            int row = rem >> 4, col = rem & 15;
            const __half* src;
            if (arr < 2) {
                src = (arr == 0 ? A0 : A1) + (size_t)(k0 + row) * THW + t0 + col * 8;
            } else {
                src = (arr == 2 ? B0 : B1) + (size_t)(k0 + row) * HW + q0 + col * 8;
            }
            cp16(sb + (uint32_t)arr * (G1_TILE * 2) + row * (TP * 2) + col * 16, src);
        }
    };

    wmma::fragment<wmma::accumulator, 16, 16, 16, float> fc[4][4];
    #pragma unroll
    for (int i = 0; i < 4; i++)
        #pragma unroll
        for (int j = 0; j < 4; j++) wmma::fill_fragment(fc[i][j], 0.f);

    const int NC = DE / 32;   // 4
    load_stage(0, 0);
    CP_COMMIT();

    for (int c = 0; c < NC; c++) {
        if (c + 1 < NC) { load_stage((c + 1) & 1, (c + 1) * 32); CP_COMMIT(); }
        if (c + 1 < NC) CP_WAIT(1); else CP_WAIT(0);
        __syncthreads();

        __half* st = dsm + (size_t)(c & 1) * G1_STAGE;
        #pragma unroll
        for (int kk = 0; kk < 32; kk += 16) {
            wmma::fragment<wmma::matrix_a, 16, 16, 16, __half, wmma::col_major> fa[2][4];
            wmma::fragment<wmma::matrix_b, 16, 16, 16, __half, wmma::row_major> fb[2][4];
            #pragma unroll
            for (int l = 0; l < 2; l++)
                #pragma unroll
                for (int i = 0; i < 4; i++)
                    wmma::load_matrix_sync(fa[l][i],
                        st + l * G1_TILE + kk * TP + wm * 64 + i * 16, TP);
            #pragma unroll
            for (int l = 0; l < 2; l++)
                #pragma unroll
                for (int j = 0; j < 4; j++)
                    wmma::load_matrix_sync(fb[l][j],
                        st + (2 + l) * G1_TILE + kk * TP + wn * 64 + j * 16, TP);
            #pragma unroll
            for (int i = 0; i < 4; i++)
                #pragma unroll
                for (int j = 0; j < 4; j++)
                    wmma::mma_sync(fc[i][j], fa[0][i], fb[0][j], fc[i][j]);
            #pragma unroll
            for (int i = 0; i < 4; i++)
                #pragma unroll
                for (int j = 0; j < 4; j++)
                    wmma::mma_sync(fc[i][j], fa[0][i], fb[1][j], fc[i][j]);
            #pragma unroll
            for (int i = 0; i < 4; i++)
                #pragma unroll
                for (int j = 0; j < 4; j++)
                    wmma::mma_sync(fc[i][j], fa[1][i], fb[0][j], fc[i][j]);
        }
        __syncthreads();
    }

    // epilogue via smem: 128x128 fp32 tile
    float* sc = (float*)dsm;
    #pragma unroll
    for (int i = 0; i < 4; i++)
        #pragma unroll
        for (int j = 0; j < 4; j++)
            wmma::store_matrix_sync(sc + (size_t)(wm * 64 + i * 16) * 128 + wn * 64 + j * 16,
                                    fc[i][j], 128, wmma::mem_row_major);
    __syncthreads();

    // coalesced p store
    float* C = p + ((size_t)b * THW + t0) * HW + q0;
    #pragma unroll
    for (int l = 0; l < 32; l++) {
        int i = tid + l * 128;                   // 0..4095 float4
        int row = i >> 5, col = (i & 31) << 2;
        *(float4*)(C + (size_t)row * HW + col) = *(float4*)(sc + row * 128 + col);
    }

    // fused argmax partial: 1 thread per row, ROTATED scan (bank-conflict-free)
    {
        int row = tid;
        const float* r = sc + row * 128;
        int c0 = tid & 127;
        float bv = r[c0];
        int bj = c0;
        #pragma unroll 8
        for (int k = 1; k < 128; k++) {
            int col = (k + tid) & 127;
            float v = r[col];
            if (v > bv || (v == bv && col < bj)) { bv = v; bj = col; }
        }
        g_amax[((size_t)b * THW + t0 + row) * 8 + blockIdx.x] =
            make_float2(bv, (float)(q0 + bj));
    }
}

// reduce 8 tile-partials per row -> gaussian center
__global__ void __launch_bounds__(256) argmax_final()
{
    int r = blockIdx.x * 256 + threadIdx.x;
    if (r >= B_ * THW) return;
    const float2* a = g_amax + (size_t)r * 8;
    float bv = a[0].x;
    int bi = (int)a[0].y;
    #pragma unroll
    for (int k = 1; k < 8; k++) {
        float2 v = a[k];
        if (v.x > bv) { bv = v.x; bi = (int)v.y; }
    }
    g_center[r] = make_float2((float)(bi & 31), (float)(bi >> 5));
}

// ============================================================
// exp + transpose: e^T fp16 hi only + partial sums (p preserved)
// ============================================================
__global__ void __launch_bounds__(256) exp_t_kernel(const float* __restrict__ p)
{
    __shared__ float tile[32][129];    // [q][t]
    __shared__ float ssum[8][32];
    const int b = blockIdx.z, t0 = blockIdx.y * 128, q0 = blockIdx.x * 32;
    const int tid = threadIdx.x, tx = tid & 31, ty = tid >> 5;
    const float qx = (float)((q0 + tx) & 31), qy = (float)((q0 + tx) >> 5);
    const float* pc = p + ((size_t)b * THW + t0) * HW + q0 + tx;
    const float2* cen = g_center + (size_t)b * THW + t0;
    float s = 0.f;
    #pragma unroll 4
    for (int r = 0; r < 16; r++) {
        int t = ty * 16 + r;
        float2 c = cen[t];
        float dx = qx - c.x, dy = qy - c.y;
        float v = __expf(pc[(size_t)t * HW] - (dx * dx + dy * dy) * INV2SIG2);
        tile[tx][t] = v;
        s += v;
    }
    ssum[ty][tx] = s;
    __syncthreads();
    if (ty == 0) {
        float a = 0.f;
        #pragma unroll
        for (int k = 0; k < 8; k++) a += ssum[k][tx];
        g_part[((size_t)b * NCHUNK + blockIdx.y) * HW + q0 + tx] = a;
    }
    const int qq = tid >> 3, seg = tid & 7;
    uint32_t hi[8];
    #pragma unroll
    for (int k = 0; k < 8; k++) {
        __half h0 = __float2half(tile[qq][seg * 16 + 2 * k]);
        __half h1 = __float2half(tile[qq][seg * 16 + 2 * k + 1]);
        hi[k] = ((uint32_t)*(uint16_t*)&h1 << 16) | *(uint16_t*)&h0;
    }
    size_t o = ((size_t)b * HW + q0 + qq) * THW + t0 + seg * 16;
    *(uint4*)(g_ehi + o)     = make_uint4(hi[0], hi[1], hi[2], hi[3]);
    *(uint4*)(g_ehi + o + 8) = make_uint4(hi[4], hi[5], hi[6], hi[7]);
}

__global__ void __launch_bounds__(256) inv_kernel()
{
    int i = blockIdx.x * 256 + threadIdx.x;
    int b = i >> 10, q = i & 1023;
    float s = 0.f;
    #pragma unroll
    for (int c = 0; c < NCHUNK; c++) s += g_part[((size_t)b * NCHUNK + c) * HW + q];
    g_inv[i] = 1.0f / s;
}

// ============================================================
// WMMA fp16 GEMM2: D = mo_hi . e_hi^T  (1 pass)
// CTA 128(o) x 128(q), 4 warps @64x64, K-chunk 32, 3-stage,
// split-K=2 -> 256 CTAs (one 2-CTA/SM wave, 16 warps/SM)
// ============================================================
#define KP 40
#define G2_TILE (128 * KP)
#define G2_STAGE (2 * G2_TILE)                  // 10240 elems
#define G2_SMEM (3 * G2_STAGE * 2)              // 61440 bytes

__global__ void __launch_bounds__(128, 2) gemm2_wmma()
{
    extern __shared__ __half dsm[];
    const int b = blockIdx.z >> 1, half_ = blockIdx.z & 1;
    const int kbase = half_ * (THW / 2);
    const int q0 = blockIdx.x * 128, o0 = blockIdx.y * 128;
    const int tid = threadIdx.x, wid = tid >> 5;
    const int wm = wid & 1, wn = wid >> 1;       // 2x2 warps, tile 64(o) x 64(q)

    const __half* Ah = g_mohi + ((size_t)b * DO + o0) * THW + kbase;
    const __half* Bh = g_ehi  + ((size_t)b * HW + q0) * THW + kbase;

    const uint32_t sbase = (uint32_t)__cvta_generic_to_shared(dsm);

    auto load_stage = [&](int slot, int kc) {
        uint32_t sb = sbase + (uint32_t)slot * (G2_STAGE * 2);
        #pragma unroll
        for (int l = 0; l < 8; l++) {
            int idx = tid + l * 128;             // 0..1023
            if (idx < 512) {                     // A hi: 128 rows x 4 cp16
                int r = idx >> 2, ch = idx & 3;
                cp16(sb + r * (KP * 2) + ch * 16, Ah + (size_t)r * THW + kc + ch * 8);
            } else {                             // B hi: 128 rows x 4 cp16
                int idx2 = idx - 512;
                int r = idx2 >> 2, ch = idx2 & 3;
                cp16(sb + (uint32_t)G2_TILE * 2 + r * (KP * 2) + ch * 16,
                     Bh + (size_t)r * THW + kc + ch * 8);
            }
        }
    };

    wmma::fragment<wmma::accumulator, 16, 16, 16, float> fc[4][4];
    #pragma unroll
    for (int i = 0; i < 4; i++)
        #pragma unroll
        for (int j = 0; j < 4; j++) wmma::fill_fragment(fc[i][j], 0.f);

    const int NC = (THW / 2) / 32;   // 160

    load_stage(0, 0);  CP_COMMIT();
    load_stage(1, 32); CP_COMMIT();

    for (int c = 0; c < NC; c++) {
        CP_WAIT(1);
        __syncthreads();
        if (c + 2 < NC) { load_stage((c + 2) % 3, (c + 2) * 32); CP_COMMIT(); }

        __half* st  = dsm + (size_t)(c % 3) * G2_STAGE;
        __half* tAh = st;
        __half* tBh = st + G2_TILE;

        #pragma unroll
        for (int kk = 0; kk < 32; kk += 16) {
            wmma::fragment<wmma::matrix_a, 16, 16, 16, __half, wmma::row_major> fah[4];
            #pragma unroll
            for (int i = 0; i < 4; i++)
                wmma::load_matrix_sync(fah[i], tAh + (wm * 64 + i * 16) * KP + kk, KP);
            #pragma unroll
            for (int j = 0; j < 4; j++) {
                wmma::fragment<wmma::matrix_b, 16, 16, 16, __half, wmma::col_major> fbh;
                wmma::load_matrix_sync(fbh, tBh + (wn * 64 + j * 16) * KP + kk, KP);
                #pragma unroll
                for (int i = 0; i < 4; i++)
                    wmma::mma_sync(fc[i][j], fah[i], fbh, fc[i][j]);
            }
        }
    }
    CP_WAIT(0);

    float* C = g_cpart + (((size_t)half_ * B_ + b) * DO + o0 + wm * 64) * HW + q0 + wn * 64;
    #pragma unroll
    for (int i = 0; i < 4; i++)
        #pragma unroll
        for (int j = 0; j < 4; j++)
            wmma::store_matrix_sync(C + (size_t)(i * 16) * HW + j * 16,
                                    fc[i][j], HW, wmma::mem_row_major);
}

// combine split-K halves + apply inv -> out[:, :Do]; also copy q_out -> out[:, Do:]
__global__ void __launch_bounds__(256) combine_kernel(
    const float* __restrict__ q_out, float* __restrict__ out)
{
    const size_t n4 = (size_t)B_ * DO * HW / 4;
    size_t i = (size_t)blockIdx.x * 256 + threadIdx.x;
    if (i >= n4) return;
    float4 a = ((const float4*)g_cpart)[i];
    float4 c = ((const float4*)g_cpart)[i + n4];
    size_t q4 = i & 255;
    size_t b  = i / ((size_t)DO * HW / 4);
    float4 inv = ((const float4*)g_inv)[b * 256 + q4];
    float4 v = make_float4((a.x + c.x) * inv.x, (a.y + c.y) * inv.y,
                           (a.z + c.z) * inv.z, (a.w + c.w) * inv.w);
    const size_t per = (size_t)DO * HW / 4;
    size_t r = i - b * per;
    ((float4*)out)[b * 2 * per + r] = v;
    ((float4*)out)[b * 2 * per + per + r] = ((const float4*)q_out)[i];
}

// p_w fp32 output from ehi: transpose [b][q][t] -> [b][t][q], *inv
__global__ void __launch_bounds__(256) pw_t_kernel(float* __restrict__ dst)
{
    __shared__ float tile[32][129];
    __shared__ float sinv[32];
    const int b = blockIdx.z, t0 = blockIdx.y * 128, q0 = blockIdx.x * 32;
    const int tid = threadIdx.x;

    {
        int q = tid >> 3, seg = tid & 7;
        size_t o = ((size_t)b * HW + q0 + q) * THW + t0 + seg * 16;
        uint4 h0 = *(const uint4*)(g_ehi + o);
        uint4 h1 = *(const uint4*)(g_ehi + o + 8);
        const uint32_t hw_[8] = {h0.x, h0.y, h0.z, h0.w, h1.x, h1.y, h1.z, h1.w};
        #pragma unroll
        for (int k = 0; k < 8; k++) {
            __half2 hv = *(const __half2*)&hw_[k];
            tile[q][seg * 16 + 2 * k]     = __half2float(hv.x);
            tile[q][seg * 16 + 2 * k + 1] = __half2float(hv.y);
        }
    }
    if (tid < 32) sinv[tid] = g_inv[(size_t)b * HW + q0 + tid];
    __syncthreads();

    int t = tid >> 1, qs = (tid & 1) * 16;
    float* d = dst + ((size_t)b * THW + t0 + t) * HW + q0 + qs;
    #pragma unroll
    for (int k = 0; k < 16; k += 4) {
        float4 v = make_float4(tile[qs + k][t]     * sinv[qs + k],
                               tile[qs + k + 1][t] * sinv[qs + k + 1],
                               tile[qs + k + 2][t] * sinv[qs + k + 2],
                               tile[qs + k + 3][t] * sinv[qs + k + 3]);
        *(float4*)(d + k) = v;
    }
}

// ============================================================
extern "C" void kernel_launch(void* const* d_in, const int* in_sizes, int n_in,
                              void* d_out, int out_size)
{
    const float* m_in  = (const float*)d_in[0];
    const float* m_out = (const float*)d_in[1];
    const float* q_in  = (const float*)d_in[2];
    const float* q_out = (const float*)d_in[3];
    float* out = (float*)d_out;

    float* p = nullptr;
    cudaGetSymbolAddress((void**)&p, g_p);
    __half *mi0, *mi1, *qi0, *qi1, *moh;
    cudaGetSymbolAddress((void**)&mi0, g_mi0);
    cudaGetSymbolAddress((void**)&mi1, g_mi1);
    cudaGetSymbolAddress((void**)&qi0, g_qi0);
    cudaGetSymbolAddress((void**)&qi1, g_qi1);
    cudaGetSymbolAddress((void**)&moh, g_mohi);

    cudaFuncSetAttribute(gemm1_wmma, cudaFuncAttributeMaxDynamicSharedMemorySize, G1_SMEM);
    cudaFuncSetAttribute(gemm2_wmma, cudaFuncAttributeMaxDynamicSharedMemorySize, G2_SMEM);

    // 0) split mi, qi*SCALE into fp16 2-limb; mo hi-only
    split2h_kernel<<<2048, 256>>>(m_in, mi0, mi1, (size_t)B_ * DE * THW / 4, 1.0f);
    split2h_kernel<<<512, 256>>>(q_in, qi0, qi1, (size_t)B_ * DE * HW / 4, SCALE);
    split1h_kernel<<<2048, 256>>>(m_out, moh, (size_t)B_ * DO * THW / 4);

    // 1) p = mi^T (qi*SCALE) via WMMA fp16 2-limb, 64x64 warp tiles
    dim3 g1(HW / 128, THW / 128, B_);   // (8, 80, 4)
    gemm1_wmma<<<g1, 128, G1_SMEM>>>(p);

    // 2) argmax final reduce -> centers
    argmax_final<<<(B_ * THW + 255) / 256, 256>>>();

    // 3) exp + transpose (hi only) + partial sums
    dim3 g3(HW / 32, THW / 128, B_);
    exp_t_kernel<<<g3, 256>>>(p);

    // 4) inv
    inv_kernel<<<(B_ * HW) / 256, 256>>>();

    // 5) WMMA fp16 GEMM2 (1 pass), CTA 128x128, split-K=2 -> 256 CTAs
    dim3 g4(HW / 128, DO / 128, B_ * 2);   // (8, 4, 8)
    gemm2_wmma<<<g4, 128, G2_SMEM>>>();

    // 6) combine halves + normalize + qout copy
    combine_kernel<<<(B_ * DO * HW / 4 + 255) / 256, 256>>>(q_out, out);

    // 7) optional p_w output (hi only)
    const size_t memout = (size_t)B_ * 2 * DO * HW;
    const size_t pw     = (size_t)B_ * THW * HW;
    if ((size_t)out_size >= memout + pw) {
        dim3 g5(HW / 32, THW / 128, B_);
        pw_t_kernel<<<g5, 256>>>(out + memout);
    }
}

// round 16
// speedup vs baseline: 2.1054x; 1.0077x over previous
#include <cuda_runtime.h>
#include <cuda_fp16.h>
#include <mma.h>
#include <cstdint>
#include <math.h>

using namespace nvcuda;

#define B_    4
#define DE    128
#define DO    512
#define THW   10240
#define HW    1024
#define NCHUNK 80
#define SCALE 0.08838834764831845f
#define INV2SIG2 (1.0f/18.0f)

// ---------------- device scratch ----------------
__device__ float  g_p[(size_t)B_ * THW * HW];       // p fp32
__device__ __half g_eh[(size_t)B_ * THW * HW];      // e [b][t][q] fp16 (natural layout)
__device__ __half g_mohi[(size_t)B_ * DO * THW];    // mo fp16 hi
__device__ __half g_mi0[(size_t)B_ * DE * THW];     // mi 2 limbs [b][d][t]
__device__ __half g_mi1[(size_t)B_ * DE * THW];
__device__ __half g_qi0[(size_t)B_ * DE * HW];      // qi*SCALE 2 limbs [b][d][q]
__device__ __half g_qi1[(size_t)B_ * DE * HW];
__device__ float  g_cpart[(size_t)2 * B_ * DO * HW];
__device__ float2 g_center[B_ * THW];
__device__ float2 g_amax[(size_t)B_ * THW * 8];
__device__ float  g_part[(size_t)B_ * NCHUNK * HW];
__device__ float  g_inv[B_ * HW];

__device__ __forceinline__ void cp16(uint32_t sa, const void* g) {
    asm volatile("cp.async.cg.shared.global [%0], [%1], 16;" :: "r"(sa), "l"(g));
}
#define CP_COMMIT() asm volatile("cp.async.commit_group;" ::: "memory")
#define CP_WAIT(n)  asm volatile("cp.async.wait_group %0;" :: "n"(n) : "memory")

// ============================================================
// split fp32 -> 2 fp16 limbs (optional scale)
// ============================================================
__global__ void __launch_bounds__(256) split2h_kernel(
    const float* __restrict__ in, __half* __restrict__ o0,
    __half* __restrict__ o1, size_t n4, float scale)
{
    const size_t stride = (size_t)gridDim.x * 256;
    for (size_t i = (size_t)blockIdx.x * 256 + threadIdx.x; i < n4; i += stride) {
        float4 v = ((const float4*)in)[i];
        float f[4] = {v.x * scale, v.y * scale, v.z * scale, v.w * scale};
        uint16_t l0[4], l1[4];
        #pragma unroll
        for (int k = 0; k < 4; k++) {
            __half h = __float2half(f[k]);
            __half l = __float2half(f[k] - __half2float(h));
            l0[k] = *(uint16_t*)&h;
            l1[k] = *(uint16_t*)&l;
        }
        ((uint2*)o0)[i] = make_uint2(l0[0] | ((uint32_t)l0[1] << 16), l0[2] | ((uint32_t)l0[3] << 16));
        ((uint2*)o1)[i] = make_uint2(l1[0] | ((uint32_t)l1[1] << 16), l1[2] | ((uint32_t)l1[3] << 16));
    }
}

// split fp32 -> fp16 hi only
__global__ void __launch_bounds__(256) split1h_kernel(
    const float* __restrict__ in, __half* __restrict__ o0, size_t n4)
{
    const size_t stride = (size_t)gridDim.x * 256;
    for (size_t i = (size_t)blockIdx.x * 256 + threadIdx.x; i < n4; i += stride) {
        float4 v = ((const float4*)in)[i];
        __half h0 = __float2half(v.x), h1 = __float2half(v.y);
        __half h2 = __float2half(v.z), h3 = __float2half(v.w);
        uint16_t u0 = *(uint16_t*)&h0, u1 = *(uint16_t*)&h1;
        uint16_t u2 = *(uint16_t*)&h2, u3 = *(uint16_t*)&h3;
        ((uint2*)o0)[i] = make_uint2(u0 | ((uint32_t)u1 << 16), u2 | ((uint32_t)u3 << 16));
    }
}

// ============================================================
// WMMA fp16 GEMM1 (2-limb, 3 passes): p = (mi)^T (qi*SCALE)
// 128 threads / 4 warps (2x2), warp tile 64(t) x 64(q), 2 CTAs/SM
// ============================================================
#define TP 136
#define G1_TILE (32 * TP)
#define G1_STAGE (4 * G1_TILE)
#define G1_SMEM (2 * G1_STAGE * 2)              // 69632 bytes

__global__ void __launch_bounds__(128, 2) gemm1_wmma(float* __restrict__ p)
{
    extern __shared__ __half dsm[];
    const int b = blockIdx.z;
    const int q0 = blockIdx.x * 128, t0 = blockIdx.y * 128;
    const int tid = threadIdx.x, wid = tid >> 5;
    const int wm = wid & 1, wn = wid >> 1;

    const __half* A0 = g_mi0 + (size_t)b * DE * THW;
    const __half* A1 = g_mi1 + (size_t)b * DE * THW;
    const __half* B0 = g_qi0 + (size_t)b * DE * HW;
    const __half* B1 = g_qi1 + (size_t)b * DE * HW;

    const uint32_t sbase = (uint32_t)__cvta_generic_to_shared(dsm);

    auto load_stage = [&](int slot, int k0) {
        uint32_t sb = sbase + (uint32_t)slot * (G1_STAGE * 2);
        #pragma unroll
        for (int l = 0; l < 16; l++) {
            int idx = tid + l * 128;             // 0..2047
            int arr = idx >> 9, rem = idx & 511;
            int row = rem >> 4, col = rem & 15;
            const __half* src;
            if (arr < 2) {
                src = (arr == 0 ? A0 : A1) + (size_t)(k0 + row) * THW + t0 + col * 8;
            } else {
                src = (arr == 2 ? B0 : B1) + (size_t)(k0 + row) * HW + q0 + col * 8;
            }
            cp16(sb + (uint32_t)arr * (G1_TILE * 2) + row * (TP * 2) + col * 16, src);
        }
    };

    wmma::fragment<wmma::accumulator, 16, 16, 16, float> fc[4][4];
    #pragma unroll
    for (int i = 0; i < 4; i++)
        #pragma unroll
        for (int j = 0; j < 4; j++) wmma::fill_fragment(fc[i][j], 0.f);

    const int NC = DE / 32;   // 4
    load_stage(0, 0);
    CP_COMMIT();

    for (int c = 0; c < NC; c++) {
        if (c + 1 < NC) { load_stage((c + 1) & 1, (c + 1) * 32); CP_COMMIT(); }
        if (c + 1 < NC) CP_WAIT(1); else CP_WAIT(0);
        __syncthreads();

        __half* st = dsm + (size_t)(c & 1) * G1_STAGE;
        #pragma unroll
        for (int kk = 0; kk < 32; kk += 16) {
            wmma::fragment<wmma::matrix_a, 16, 16, 16, __half, wmma::col_major> fa[2][4];
            wmma::fragment<wmma::matrix_b, 16, 16, 16, __half, wmma::row_major> fb[2][4];
            #pragma unroll
            for (int l = 0; l < 2; l++)
                #pragma unroll
                for (int i = 0; i < 4; i++)
                    wmma::load_matrix_sync(fa[l][i],
                        st + l * G1_TILE + kk * TP + wm * 64 + i * 16, TP);
            #pragma unroll
            for (int l = 0; l < 2; l++)
                #pragma unroll
                for (int j = 0; j < 4; j++)
                    wmma::load_matrix_sync(fb[l][j],
                        st + (2 + l) * G1_TILE + kk * TP + wn * 64 + j * 16, TP);
            #pragma unroll
            for (int i = 0; i < 4; i++)
                #pragma unroll
                for (int j = 0; j < 4; j++)
                    wmma::mma_sync(fc[i][j], fa[0][i], fb[0][j], fc[i][j]);
            #pragma unroll
            for (int i = 0; i < 4; i++)
                #pragma unroll
                for (int j = 0; j < 4; j++)
                    wmma::mma_sync(fc[i][j], fa[0][i], fb[1][j], fc[i][j]);
            #pragma unroll
            for (int i = 0; i < 4; i++)
                #pragma unroll
                for (int j = 0; j < 4; j++)
                    wmma::mma_sync(fc[i][j], fa[1][i], fb[0][j], fc[i][j]);
        }
        __syncthreads();
    }

    // epilogue via smem: 128x128 fp32 tile
    float* sc = (float*)dsm;
    #pragma unroll
    for (int i = 0; i < 4; i++)
        #pragma unroll
        for (int j = 0; j < 4; j++)
            wmma::store_matrix_sync(sc + (size_t)(wm * 64 + i * 16) * 128 + wn * 64 + j * 16,
                                    fc[i][j], 128, wmma::mem_row_major);
    __syncthreads();

    float* C = p + ((size_t)b * THW + t0) * HW + q0;
    #pragma unroll
    for (int l = 0; l < 32; l++) {
        int i = tid + l * 128;
        int row = i >> 5, col = (i & 31) << 2;
        *(float4*)(C + (size_t)row * HW + col) = *(float4*)(sc + row * 128 + col);
    }

    // fused argmax partial: 1 thread per row, rotated scan (conflict-free)
    {
        int row = tid;
        const float* r = sc + row * 128;
        int c0 = tid & 127;
        float bv = r[c0];
        int bj = c0;
        #pragma unroll 8
        for (int k = 1; k < 128; k++) {
            int col = (k + tid) & 127;
            float v = r[col];
            if (v > bv || (v == bv && col < bj)) { bv = v; bj = col; }
        }
        g_amax[((size_t)b * THW + t0 + row) * 8 + blockIdx.x] =
            make_float2(bv, (float)(q0 + bj));
    }
}

__global__ void __launch_bounds__(256) argmax_final()
{
    int r = blockIdx.x * 256 + threadIdx.x;
    if (r >= B_ * THW) return;
    const float2* a = g_amax + (size_t)r * 8;
    float bv = a[0].x;
    int bi = (int)a[0].y;
    #pragma unroll
    for (int k = 1; k < 8; k++) {
        float2 v = a[k];
        if (v.x > bv) { bv = v.x; bi = (int)v.y; }
    }
    g_center[r] = make_float2((float)(bi & 31), (float)(bi >> 5));
}

// ============================================================
// exp (streaming, no transpose): e_h[b][t][q] = fp16(exp(...)),
// partial sums over 128-t blocks. Fully coalesced.
// block: 256 q-threads x 128 t rows
// ============================================================
__global__ void __launch_bounds__(256) exp_s_kernel(
    const float* __restrict__ p, __half* __restrict__ eh)
{
    const int b = blockIdx.z, t0 = blockIdx.y * 128, q0 = blockIdx.x * 256;
    const int q = q0 + threadIdx.x;
    const float qx = (float)(q & 31), qy = (float)(q >> 5);
    const float* pc = p + ((size_t)b * THW + t0) * HW + q;
    __half* ec = eh + ((size_t)b * THW + t0) * HW + q;
    const float2* cen = g_center + (size_t)b * THW + t0;
    float s = 0.f;
    #pragma unroll 4
    for (int r = 0; r < 128; r++) {
        float2 c = cen[r];
        float dx = qx - c.x, dy = qy - c.y;
        float v = __expf(pc[(size_t)r * HW] - (dx * dx + dy * dy) * INV2SIG2);
        ec[(size_t)r * HW] = __float2half(v);
        s += v;
    }
    g_part[((size_t)b * NCHUNK + blockIdx.y) * HW + q] = s;
}

__global__ void __launch_bounds__(256) inv_kernel()
{
    int i = blockIdx.x * 256 + threadIdx.x;
    int b = i >> 10, q = i & 1023;
    float s = 0.f;
    #pragma unroll
    for (int c = 0; c < NCHUNK; c++) s += g_part[((size_t)b * NCHUNK + c) * HW + q];
    g_inv[i] = 1.0f / s;
}

// ============================================================
// WMMA fp16 GEMM2: D = mo_hi . e_h   (1 pass, B natural [t][q])
// CTA 128(o) x 128(q), 4 warps @64x64, K-chunk 32, 3-stage,
// split-K=2 -> 256 CTAs
// ============================================================
#define KP 40
#define BQ 136
#define G2_A_E (128 * KP)                       // 5120
#define G2_B_E (32 * BQ)                        // 4352
#define G2_STAGE (G2_A_E + G2_B_E)              // 9472 halfs
#define G2_SMEM (3 * G2_STAGE * 2)              // 56832 bytes

__global__ void __launch_bounds__(128, 2) gemm2_wmma()
{
    extern __shared__ __half dsm[];
    const int b = blockIdx.z >> 1, half_ = blockIdx.z & 1;
    const int kbase = half_ * (THW / 2);
    const int q0 = blockIdx.x * 128, o0 = blockIdx.y * 128;
    const int tid = threadIdx.x, wid = tid >> 5;
    const int wm = wid & 1, wn = wid >> 1;

    const __half* Ah = g_mohi + ((size_t)b * DO + o0) * THW + kbase;
    const __half* Be = g_eh + ((size_t)b * THW + kbase) * HW + q0;

    const uint32_t sbase = (uint32_t)__cvta_generic_to_shared(dsm);

    auto load_stage = [&](int slot, int kc) {
        uint32_t sb = sbase + (uint32_t)slot * (G2_STAGE * 2);
        #pragma unroll
        for (int l = 0; l < 8; l++) {
            int idx = tid + l * 128;             // 0..1023
            if (idx < 512) {                     // A: 128 rows(o) x 4 cp16 (k)
                int r = idx >> 2, ch = idx & 3;
                cp16(sb + r * (KP * 2) + ch * 16, Ah + (size_t)r * THW + kc + ch * 8);
            } else {                             // B: 32 rows(k) x 16 cp16 (q)
                int idx2 = idx - 512;            // 0..511
                int kr = idx2 >> 4, ch = idx2 & 15;
                cp16(sb + (uint32_t)G2_A_E * 2 + kr * (BQ * 2) + ch * 16,
                     Be + (size_t)(kc + kr) * HW + ch * 8);
            }
        }
    };

    wmma::fragment<wmma::accumulator, 16, 16, 16, float> fc[4][4];
    #pragma unroll
    for (int i = 0; i < 4; i++)
        #pragma unroll
        for (int j = 0; j < 4; j++) wmma::fill_fragment(fc[i][j], 0.f);

    const int NC = (THW / 2) / 32;   // 160

    load_stage(0, 0);  CP_COMMIT();
    load_stage(1, 32); CP_COMMIT();

    for (int c = 0; c < NC; c++) {
        CP_WAIT(1);
        __syncthreads();
        if (c + 2 < NC) { load_stage((c + 2) % 3, (c + 2) * 32); CP_COMMIT(); }

        __half* st  = dsm + (size_t)(c % 3) * G2_STAGE;
        __half* tAh = st;
        __half* tBe = st + G2_A_E;

        #pragma unroll
        for (int kk = 0; kk < 32; kk += 16) {
            wmma::fragment<wmma::matrix_a, 16, 16, 16, __half, wmma::row_major> fah[4];
            #pragma unroll
            for (int i = 0; i < 4; i++)
                wmma::load_matrix_sync(fah[i], tAh + (wm * 64 + i * 16) * KP + kk, KP);
            #pragma unroll
            for (int j = 0; j < 4; j++) {
                wmma::fragment<wmma::matrix_b, 16, 16, 16, __half, wmma::row_major> fbh;
                wmma::load_matrix_sync(fbh, tBe + kk * BQ + wn * 64 + j * 16, BQ);
                #pragma unroll
                for (int i = 0; i < 4; i++)
                    wmma::mma_sync(fc[i][j], fah[i], fbh, fc[i][j]);
            }
        }
    }
    CP_WAIT(0);

    float* C = g_cpart + (((size_t)half_ * B_ + b) * DO + o0 + wm * 64) * HW + q0 + wn * 64;
    #pragma unroll
    for (int i = 0; i < 4; i++)
        #pragma unroll
        for (int j = 0; j < 4; j++)
            wmma::store_matrix_sync(C + (size_t)(i * 16) * HW + j * 16,
                                    fc[i][j], HW, wmma::mem_row_major);
}

// combine split-K halves + apply inv -> out[:, :Do]; copy q_out -> out[:, Do:]
__global__ void __launch_bounds__(256) combine_kernel(
    const float* __restrict__ q_out, float* __restrict__ out)
{
    const size_t n4 = (size_t)B_ * DO * HW / 4;
    size_t i = (size_t)blockIdx.x * 256 + threadIdx.x;
    if (i >= n4) return;
    float4 a = ((const float4*)g_cpart)[i];
    float4 c = ((const float4*)g_cpart)[i + n4];
    size_t q4 = i & 255;
    size_t b  = i / ((size_t)DO * HW / 4);
    float4 inv = ((const float4*)g_inv)[b * 256 + q4];
    float4 v = make_float4((a.x + c.x) * inv.x, (a.y + c.y) * inv.y,
                           (a.z + c.z) * inv.z, (a.w + c.w) * inv.w);
    const size_t per = (size_t)DO * HW / 4;
    size_t r = i - b * per;
    ((float4*)out)[b * 2 * per + r] = v;
    ((float4*)out)[b * 2 * per + per + r] = ((const float4*)q_out)[i];
}

// p_w fp32 output: streaming pw[b][t][q] = e_h * inv[b][q]
__global__ void __launch_bounds__(256) pw_s_kernel(float* __restrict__ dst)
{
    const size_t n8 = (size_t)B_ * THW * HW / 8;
    const size_t stride = (size_t)gridDim.x * 256;
    for (size_t i = (size_t)blockIdx.x * 256 + threadIdx.x; i < n8; i += stride) {
        uint4 e8 = ((const uint4*)g_eh)[i];
        size_t i8 = i * 8;
        size_t q = i8 & (HW - 1);
        size_t b = i8 / ((size_t)THW * HW);
        const float* invp = g_inv + b * HW + q;
        float4 i0 = *(const float4*)invp;
        float4 i1 = *(const float4*)(invp + 4);
        const uint32_t w[4] = {e8.x, e8.y, e8.z, e8.w};
        float4 r0, r1;
        __half2 h0 = *(const __half2*)&w[0];
        __half2 h1 = *(const __half2*)&w[1];
        __half2 h2 = *(const __half2*)&w[2];
        __half2 h3 = *(const __half2*)&w[3];
        r0.x = __half2float(h0.x) * i0.x; r0.y = __half2float(h0.y) * i0.y;
        r0.z = __half2float(h1.x) * i0.z; r0.w = __half2float(h1.y) * i0.w;
        r1.x = __half2float(h2.x) * i1.x; r1.y = __half2float(h2.y) * i1.y;
        r1.z = __half2float(h3.x) * i1.z; r1.w = __half2float(h3.y) * i1.w;
        ((float4*)dst)[2 * i]     = r0;
        ((float4*)dst)[2 * i + 1] = r1;
    }
}

// ============================================================
extern "C" void kernel_launch(void* const* d_in, const int* in_sizes, int n_in,
                              void* d_out, int out_size)
{
    const float* m_in  = (const float*)d_in[0];
    const float* m_out = (const float*)d_in[1];
    const float* q_in  = (const float*)d_in[2];
    const float* q_out = (const float*)d_in[3];
    float* out = (float*)d_out;

    float* p = nullptr;
    cudaGetSymbolAddress((void**)&p, g_p);
    __half *mi0, *mi1, *qi0, *qi1, *moh, *eh;
    cudaGetSymbolAddress((void**)&mi0, g_mi0);
    cudaGetSymbolAddress((void**)&mi1, g_mi1);
    cudaGetSymbolAddress((void**)&qi0, g_qi0);
    cudaGetSymbolAddress((void**)&qi1, g_qi1);
    cudaGetSymbolAddress((void**)&moh, g_mohi);
    cudaGetSymbolAddress((void**)&eh, g_eh);

    cudaFuncSetAttribute(gemm1_wmma, cudaFuncAttributeMaxDynamicSharedMemorySize, G1_SMEM);
    cudaFuncSetAttribute(gemm2_wmma, cudaFuncAttributeMaxDynamicSharedMemorySize, G2_SMEM);

    // 0) splits
    split2h_kernel<<<2048, 256>>>(m_in, mi0, mi1, (size_t)B_ * DE * THW / 4, 1.0f);
    split2h_kernel<<<512, 256>>>(q_in, qi0, qi1, (size_t)B_ * DE * HW / 4, SCALE);
    split1h_kernel<<<2048, 256>>>(m_out, moh, (size_t)B_ * DO * THW / 4);

    // 1) p = mi^T (qi*SCALE) + argmax partials
    dim3 g1(HW / 128, THW / 128, B_);
    gemm1_wmma<<<g1, 128, G1_SMEM>>>(p);

    // 2) argmax final -> centers
    argmax_final<<<(B_ * THW + 255) / 256, 256>>>();

    // 3) exp streaming (natural [t][q] layout, no transpose)
    dim3 g3(HW / 256, THW / 128, B_);   // (4, 80, 4)
    exp_s_kernel<<<g3, 256>>>(p, eh);

    // 4) inv
    inv_kernel<<<(B_ * HW) / 256, 256>>>();

    // 5) GEMM2 (1 pass), split-K=2 -> 256 CTAs
    dim3 g4(HW / 128, DO / 128, B_ * 2);
    gemm2_wmma<<<g4, 128, G2_SMEM>>>();

    // 6) combine + normalize + qout copy
    combine_kernel<<<(B_ * DO * HW / 4 + 255) / 256, 256>>>(q_out, out);

    // 7) optional p_w output (streaming)
    const size_t memout = (size_t)B_ * 2 * DO * HW;
    const size_t pw     = (size_t)B_ * THW * HW;
    if ((size_t)out_size >= memout + pw)
        pw_s_kernel<<<4096, 256>>>(out + memout);
}

// round 17
// speedup vs baseline: 2.2448x; 1.0662x over previous
#include <cuda_runtime.h>
#include <cuda_fp16.h>
#include <mma.h>
#include <cstdint>
#include <math.h>
#include <float.h>

using namespace nvcuda;

#define B_    4
#define DE    128
#define DO    512
#define THW   10240
#define HW    1024
#define NCHUNK 320
#define SCALE 0.08838834764831845f
#define INV2SIG2 (1.0f/18.0f)

// ---------------- device scratch ----------------
__device__ __half g_eh[(size_t)B_ * THW * HW];      // e [b][t][q] fp16
__device__ __half g_mohi[(size_t)B_ * DO * THW];    // mo fp16 hi
__device__ __half g_mi0[(size_t)B_ * DE * THW];     // mi 2 limbs [b][d][t]
__device__ __half g_mi1[(size_t)B_ * DE * THW];
__device__ __half g_qi0[(size_t)B_ * DE * HW];      // qi*SCALE 2 limbs [b][d][q]
__device__ __half g_qi1[(size_t)B_ * DE * HW];
__device__ float  g_cpart[(size_t)2 * B_ * DO * HW];
__device__ float  g_part[(size_t)B_ * NCHUNK * HW];
__device__ float  g_inv[B_ * HW];

__device__ __forceinline__ void cp16(uint32_t sa, const void* g) {
    asm volatile("cp.async.cg.shared.global [%0], [%1], 16;" :: "r"(sa), "l"(g));
}
#define CP_COMMIT() asm volatile("cp.async.commit_group;" ::: "memory")
#define CP_WAIT(n)  asm volatile("cp.async.wait_group %0;" :: "n"(n) : "memory")

// ============================================================
// splits
// ============================================================
__global__ void __launch_bounds__(256) split2h_kernel(
    const float* __restrict__ in, __half* __restrict__ o0,
    __half* __restrict__ o1, size_t n4, float scale)
{
    const size_t stride = (size_t)gridDim.x * 256;
    for (size_t i = (size_t)blockIdx.x * 256 + threadIdx.x; i < n4; i += stride) {
        float4 v = ((const float4*)in)[i];
        float f[4] = {v.x * scale, v.y * scale, v.z * scale, v.w * scale};
        uint16_t l0[4], l1[4];
        #pragma unroll
        for (int k = 0; k < 4; k++) {
            __half h = __float2half(f[k]);
            __half l = __float2half(f[k] - __half2float(h));
            l0[k] = *(uint16_t*)&h;
            l1[k] = *(uint16_t*)&l;
        }
        ((uint2*)o0)[i] = make_uint2(l0[0] | ((uint32_t)l0[1] << 16), l0[2] | ((uint32_t)l0[3] << 16));
        ((uint2*)o1)[i] = make_uint2(l1[0] | ((uint32_t)l1[1] << 16), l1[2] | ((uint32_t)l1[3] << 16));
    }
}

__global__ void __launch_bounds__(256) split1h_kernel(
    const float* __restrict__ in, __half* __restrict__ o0, size_t n4)
{
    const size_t stride = (size_t)gridDim.x * 256;
    for (size_t i = (size_t)blockIdx.x * 256 + threadIdx.x; i < n4; i += stride) {
        float4 v = ((const float4*)in)[i];
        __half h0 = __float2half(v.x), h1 = __float2half(v.y);
        __half h2 = __float2half(v.z), h3 = __float2half(v.w);
        uint16_t u0 = *(uint16_t*)&h0, u1 = *(uint16_t*)&h1;
        uint16_t u2 = *(uint16_t*)&h2, u3 = *(uint16_t*)&h3;
        ((uint2*)o0)[i] = make_uint2(u0 | ((uint32_t)u1 << 16), u2 | ((uint32_t)u3 << 16));
    }
}

// ============================================================
// FUSED kernel: p-tile GEMM (fp16 2-limb, 3 passes) + per-row argmax
// + gaussian-softmax exp + e store + partial sums. p never hits DRAM.
// CTA: 32 t-rows x FULL 1024 q, 256 threads / 8 warps.
// Warp w: all 32 t x q-slice [128w, 128w+128). K = 128 in 8 chunks of 16.
// ============================================================
#define TA 40
#define BQ2 1032
#define FA_E (16 * TA)                    // 640 halfs per A limb tile
#define FB_E (16 * BQ2)                   // 16512 halfs per B limb tile
#define FSTAGE (2 * FA_E + 2 * FB_E)      // 34304 halfs
#define F_SMEM (3 * FSTAGE * 2)           // 205824 bytes (3-stage; epilogue reuses)

__global__ void __launch_bounds__(256) fused1_kernel()
{
    extern __shared__ __half dsm[];
    const int b = blockIdx.y, t0 = blockIdx.x * 32;
    const int tid = threadIdx.x, wid = tid >> 5;

    const __half* A0 = g_mi0 + (size_t)b * DE * THW;
    const __half* A1 = g_mi1 + (size_t)b * DE * THW;
    const __half* B0 = g_qi0 + (size_t)b * DE * HW;
    const __half* B1 = g_qi1 + (size_t)b * DE * HW;

    const uint32_t sbase = (uint32_t)__cvta_generic_to_shared(dsm);

    // stage layout (halfs): [A limb0 640][A limb1 640][B limb0 16512][B limb1 16512]
    auto load_stage = [&](int slot, int kc) {
        uint32_t sb = sbase + (uint32_t)slot * (FSTAGE * 2);
        #pragma unroll
        for (int l = 0; l < 17; l++) {
            int idx = tid + l * 256;             // 0..4351 (4224 useful)
            if (idx < 4096) {                    // B: 2 limbs x 16 k-rows x 128 cp16
                int limb = idx >> 11, row = (idx >> 7) & 15, ch = idx & 127;
                cp16(sb + (uint32_t)(2 * FA_E + limb * FB_E) * 2 + row * (BQ2 * 2) + ch * 16,
                     (limb ? B1 : B0) + (size_t)(kc + row) * HW + ch * 8);
            } else if (idx < 4224) {             // A: 2 limbs x 16 k-rows x 4 cp16
                int i2 = idx - 4096;
                int limb = i2 >> 6, row = (i2 >> 2) & 15, ch = i2 & 3;
                cp16(sb + (uint32_t)(limb * FA_E) * 2 + row * (TA * 2) + ch * 16,
                     (limb ? A1 : A0) + (size_t)(kc + row) * THW + t0 + ch * 8);
            }
        }
    };

    wmma::fragment<wmma::accumulator, 16, 16, 16, float> fc[2][8];
    #pragma unroll
    for (int i = 0; i < 2; i++)
        #pragma unroll
        for (int j = 0; j < 8; j++) wmma::fill_fragment(fc[i][j], 0.f);

    load_stage(0, 0);  CP_COMMIT();
    load_stage(1, 16); CP_COMMIT();

    for (int c = 0; c < 8; c++) {
        CP_WAIT(1);
        __syncthreads();
        if (c + 2 < 8) { load_stage((c + 2) % 3, (c + 2) * 16); CP_COMMIT(); }

        __half* st = dsm + (size_t)(c % 3) * FSTAGE;
        wmma::fragment<wmma::matrix_a, 16, 16, 16, __half, wmma::col_major> fa[2][2];
        #pragma unroll
        for (int limb = 0; limb < 2; limb++)
            #pragma unroll
            for (int i = 0; i < 2; i++)
                wmma::load_matrix_sync(fa[limb][i], st + limb * FA_E + i * 16, TA);
        __half* tB0 = st + 2 * FA_E;
        __half* tB1 = tB0 + FB_E;
        #pragma unroll
        for (int j = 0; j < 8; j++) {
            wmma::fragment<wmma::matrix_b, 16, 16, 16, __half, wmma::row_major> fb0, fb1;
            wmma::load_matrix_sync(fb0, tB0 + wid * 128 + j * 16, BQ2);
            wmma::load_matrix_sync(fb1, tB1 + wid * 128 + j * 16, BQ2);
            wmma::mma_sync(fc[0][j], fa[0][0], fb0, fc[0][j]);   // A0*B0
            wmma::mma_sync(fc[1][j], fa[0][1], fb0, fc[1][j]);
            wmma::mma_sync(fc[0][j], fa[1][0], fb0, fc[0][j]);   // A1*B0
            wmma::mma_sync(fc[1][j], fa[1][1], fb0, fc[1][j]);
            wmma::mma_sync(fc[0][j], fa[0][0], fb1, fc[0][j]);   // A0*B1
            wmma::mma_sync(fc[1][j], fa[0][1], fb1, fc[1][j]);
        }
    }
    CP_WAIT(0);
    __syncthreads();

    // ---- epilogue: p tile -> smem (32 x 1024, pitch 1028 fp32) ----
    float* out = (float*)dsm;
    float2* scen = (float2*)((char*)dsm + 32 * 1028 * 4);  // 131584 B offset
    #pragma unroll
    for (int i = 0; i < 2; i++)
        #pragma unroll
        for (int j = 0; j < 8; j++)
            wmma::store_matrix_sync(out + (size_t)(i * 16) * 1028 + wid * 128 + j * 16,
                                    fc[i][j], 1028, wmma::mem_row_major);
    __syncthreads();

    // ---- argmax per t-row: 8 threads/row, stride-8 q scan, exact ties ----
    {
        int r = tid >> 3, h = tid & 7;
        const float* rw = out + (size_t)r * 1028;
        float bv = -FLT_MAX;
        int bq = 0;
        #pragma unroll 8
        for (int k = 0; k < 128; k++) {
            int q = k * 8 + h;
            float v = rw[q];
            if (v > bv || (v == bv && q < bq)) { bv = v; bq = q; }
        }
        #pragma unroll
        for (int off = 4; off > 0; off >>= 1) {
            float ov = __shfl_down_sync(~0u, bv, off, 8);
            int   oq = __shfl_down_sync(~0u, bq, off, 8);
            if (ov > bv || (ov == bv && oq < bq)) { bv = ov; bq = oq; }
        }
        if (h == 0) scen[r] = make_float2((float)(bq & 31), (float)(bq >> 5));
    }
    __syncthreads();

    // ---- exp + e store + partial sums: thread owns 4 q columns ----
    {
        int q = tid * 4;
        float qyv = (float)(q >> 5);
        float qx0 = (float)(q & 31);
        float s0 = 0.f, s1 = 0.f, s2 = 0.f, s3 = 0.f;
        __half* ec = g_eh + ((size_t)b * THW + t0) * HW + q;
        #pragma unroll 4
        for (int t = 0; t < 32; t++) {
            float2 cc = scen[t];
            float dy = qyv - cc.y;
            float dy2 = dy * dy;
            float4 v = *(float4*)(out + (size_t)t * 1028 + q);
            float dx0 = qx0 - cc.x, dx1 = qx0 + 1.f - cc.x;
            float dx2 = qx0 + 2.f - cc.x, dx3 = qx0 + 3.f - cc.x;
            float r0 = __expf(v.x - (dx0 * dx0 + dy2) * INV2SIG2);
            float r1 = __expf(v.y - (dx1 * dx1 + dy2) * INV2SIG2);
            float r2 = __expf(v.z - (dx2 * dx2 + dy2) * INV2SIG2);
            float r3 = __expf(v.w - (dx3 * dx3 + dy2) * INV2SIG2);
            s0 += r0; s1 += r1; s2 += r2; s3 += r3;
            __half h0 = __float2half(r0), h1 = __float2half(r1);
            __half h2 = __float2half(r2), h3 = __float2half(r3);
            uint2 pk;
            pk.x = (uint32_t)*(uint16_t*)&h0 | ((uint32_t)*(uint16_t*)&h1 << 16);
            pk.y = (uint32_t)*(uint16_t*)&h2 | ((uint32_t)*(uint16_t*)&h3 << 16);
            *(uint2*)(ec + (size_t)t * HW) = pk;
        }
        *(float4*)(g_part + ((size_t)b * NCHUNK + blockIdx.x) * HW + q) =
            make_float4(s0, s1, s2, s3);
    }
}

__global__ void __launch_bounds__(256) inv_kernel()
{
    int i = blockIdx.x * 256 + threadIdx.x;
    int b = i >> 10, q = i & 1023;
    float s = 0.f;
    #pragma unroll 8
    for (int c = 0; c < NCHUNK; c++) s += g_part[((size_t)b * NCHUNK + c) * HW + q];
    g_inv[i] = 1.0f / s;
}

// ============================================================
// WMMA fp16 GEMM2: D = mo_hi . e_h  (1 pass, B natural [t][q])
// CTA 128x128, 4 warps @64x64, K-chunk 32, 3-stage, split-K=2
// ============================================================
#define KP 40
#define BQ 136
#define G2_A_E (128 * KP)
#define G2_B_E (32 * BQ)
#define G2_STAGE (G2_A_E + G2_B_E)
#define G2_SMEM (3 * G2_STAGE * 2)

__global__ void __launch_bounds__(128, 2) gemm2_wmma()
{
    extern __shared__ __half dsm[];
    const int b = blockIdx.z >> 1, half_ = blockIdx.z & 1;
    const int kbase = half_ * (THW / 2);
    const int q0 = blockIdx.x * 128, o0 = blockIdx.y * 128;
    const int tid = threadIdx.x, wid = tid >> 5;
    const int wm = wid & 1, wn = wid >> 1;

    const __half* Ah = g_mohi + ((size_t)b * DO + o0) * THW + kbase;
    const __half* Be = g_eh + ((size_t)b * THW + kbase) * HW + q0;

    const uint32_t sbase = (uint32_t)__cvta_generic_to_shared(dsm);

    auto load_stage = [&](int slot, int kc) {
        uint32_t sb = sbase + (uint32_t)slot * (G2_STAGE * 2);
        #pragma unroll
        for (int l = 0; l < 8; l++) {
            int idx = tid + l * 128;
            if (idx < 512) {
                int r = idx >> 2, ch = idx & 3;
                cp16(sb + r * (KP * 2) + ch * 16, Ah + (size_t)r * THW + kc + ch * 8);
            } else {
                int idx2 = idx - 512;
                int kr = idx2 >> 4, ch = idx2 & 15;
                cp16(sb + (uint32_t)G2_A_E * 2 + kr * (BQ * 2) + ch * 16,
                     Be + (size_t)(kc + kr) * HW + ch * 8);
            }
        }
    };

    wmma::fragment<wmma::accumulator, 16, 16, 16, float> fc[4][4];
    #pragma unroll
    for (int i = 0; i < 4; i++)
        #pragma unroll
        for (int j = 0; j < 4; j++) wmma::fill_fragment(fc[i][j], 0.f);

    const int NC = (THW / 2) / 32;   // 160

    load_stage(0, 0);  CP_COMMIT();
    load_stage(1, 32); CP_COMMIT();

    for (int c = 0; c < NC; c++) {
        CP_WAIT(1);
        __syncthreads();
        if (c + 2 < NC) { load_stage((c + 2) % 3, (c + 2) * 32); CP_COMMIT(); }

        __half* st  = dsm + (size_t)(c % 3) * G2_STAGE;
        __half* tAh = st;
        __half* tBe = st + G2_A_E;

        #pragma unroll
        for (int kk = 0; kk < 32; kk += 16) {
            wmma::fragment<wmma::matrix_a, 16, 16, 16, __half, wmma::row_major> fah[4];
            #pragma unroll
            for (int i = 0; i < 4; i++)
                wmma::load_matrix_sync(fah[i], tAh + (wm * 64 + i * 16) * KP + kk, KP);
            #pragma unroll
            for (int j = 0; j < 4; j++) {
                wmma::fragment<wmma::matrix_b, 16, 16, 16, __half, wmma::row_major> fbh;
                wmma::load_matrix_sync(fbh, tBe + kk * BQ + wn * 64 + j * 16, BQ);
                #pragma unroll
                for (int i = 0; i < 4; i++)
                    wmma::mma_sync(fc[i][j], fah[i], fbh, fc[i][j]);
            }
        }
    }
    CP_WAIT(0);

    float* C = g_cpart + (((size_t)half_ * B_ + b) * DO + o0 + wm * 64) * HW + q0 + wn * 64;
    #pragma unroll
    for (int i = 0; i < 4; i++)
        #pragma unroll
        for (int j = 0; j < 4; j++)
            wmma::store_matrix_sync(C + (size_t)(i * 16) * HW + j * 16,
                                    fc[i][j], HW, wmma::mem_row_major);
}

// combine split-K halves + inv -> out[:, :Do]; copy q_out -> out[:, Do:]
__global__ void __launch_bounds__(256) combine_kernel(
    const float* __restrict__ q_out, float* __restrict__ out)
{
    const size_t n4 = (size_t)B_ * DO * HW / 4;
    size_t i = (size_t)blockIdx.x * 256 + threadIdx.x;
    if (i >= n4) return;
    float4 a = ((const float4*)g_cpart)[i];
    float4 c = ((const float4*)g_cpart)[i + n4];
    size_t q4 = i & 255;
    size_t b  = i / ((size_t)DO * HW / 4);
    float4 inv = ((const float4*)g_inv)[b * 256 + q4];
    float4 v = make_float4((a.x + c.x) * inv.x, (a.y + c.y) * inv.y,
                           (a.z + c.z) * inv.z, (a.w + c.w) * inv.w);
    const size_t per = (size_t)DO * HW / 4;
    size_t r = i - b * per;
    ((float4*)out)[b * 2 * per + r] = v;
    ((float4*)out)[b * 2 * per + per + r] = ((const float4*)q_out)[i];
}

// p_w fp32 output: streaming pw[b][t][q] = e_h * inv[b][q]
__global__ void __launch_bounds__(256) pw_s_kernel(float* __restrict__ dst)
{
    const size_t n8 = (size_t)B_ * THW * HW / 8;
    const size_t stride = (size_t)gridDim.x * 256;
    for (size_t i = (size_t)blockIdx.x * 256 + threadIdx.x; i < n8; i += stride) {
        uint4 e8 = ((const uint4*)g_eh)[i];
        size_t i8 = i * 8;
        size_t q = i8 & (HW - 1);
        size_t b = i8 / ((size_t)THW * HW);
        const float* invp = g_inv + b * HW + q;
        float4 i0 = *(const float4*)invp;
        float4 i1 = *(const float4*)(invp + 4);
        const uint32_t w[4] = {e8.x, e8.y, e8.z, e8.w};
        __half2 h0 = *(const __half2*)&w[0];
        __half2 h1 = *(const __half2*)&w[1];
        __half2 h2 = *(const __half2*)&w[2];
        __half2 h3 = *(const __half2*)&w[3];
        float4 r0, r1;
        r0.x = __half2float(h0.x) * i0.x; r0.y = __half2float(h0.y) * i0.y;
        r0.z = __half2float(h1.x) * i0.z; r0.w = __half2float(h1.y) * i0.w;
        r1.x = __half2float(h2.x) * i1.x; r1.y = __half2float(h2.y) * i1.y;
        r1.z = __half2float(h3.x) * i1.z; r1.w = __half2float(h3.y) * i1.w;
        ((float4*)dst)[2 * i]     = r0;
        ((float4*)dst)[2 * i + 1] = r1;
    }
}

// ============================================================
extern "C" void kernel_launch(void* const* d_in, const int* in_sizes, int n_in,
                              void* d_out, int out_size)
{
    const float* m_in  = (const float*)d_in[0];
    const float* m_out = (const float*)d_in[1];
    const float* q_in  = (const float*)d_in[2];
    const float* q_out = (const float*)d_in[3];
    float* out = (float*)d_out;

    __half *mi0, *mi1, *qi0, *qi1, *moh;
    cudaGetSymbolAddress((void**)&mi0, g_mi0);
    cudaGetSymbolAddress((void**)&mi1, g_mi1);
    cudaGetSymbolAddress((void**)&qi0, g_qi0);
    cudaGetSymbolAddress((void**)&qi1, g_qi1);
    cudaGetSymbolAddress((void**)&moh, g_mohi);

    cudaFuncSetAttribute(fused1_kernel, cudaFuncAttributeMaxDynamicSharedMemorySize, F_SMEM);
    cudaFuncSetAttribute(gemm2_wmma, cudaFuncAttributeMaxDynamicSharedMemorySize, G2_SMEM);

    // 0) splits
    split2h_kernel<<<2048, 256>>>(m_in, mi0, mi1, (size_t)B_ * DE * THW / 4, 1.0f);
    split2h_kernel<<<512, 256>>>(q_in, qi0, qi1, (size_t)B_ * DE * HW / 4, SCALE);
    split1h_kernel<<<2048, 256>>>(m_out, moh, (size_t)B_ * DO * THW / 4);

    // 1) fused: GEMM1 + argmax + exp -> e_h + partial sums (p never stored)
    dim3 gf(THW / 32, B_);   // (320, 4)
    fused1_kernel<<<gf, 256, F_SMEM>>>();

    // 2) inv
    inv_kernel<<<(B_ * HW) / 256, 256>>>();

    // 3) GEMM2 (1 pass), split-K=2 -> 256 CTAs
    dim3 g4(HW / 128, DO / 128, B_ * 2);
    gemm2_wmma<<<g4, 128, G2_SMEM>>>();

    // 4) combine + normalize + qout copy
    combine_kernel<<<(B_ * DO * HW / 4 + 255) / 256, 256>>>(q_out, out);

    // 5) optional p_w output
    const size_t memout = (size_t)B_ * 2 * DO * HW;
    const size_t pw     = (size_t)B_ * THW * HW;
    if ((size_t)out_size >= memout + pw)
        pw_s_kernel<<<4096, 256>>>(out + memout);
}